// round 14
// baseline (speedup 1.0000x reference)
#include <cuda_runtime.h>
#include <cuda_fp16.h>
#include <math.h>
#include <stdint.h>

#define SEQ   1024
#define DIM   3072
#define NHDS  24
#define HD    128
#define MLPD  12288
#define CATD  15360
#define KHALF 7680
#define INV_SQRT_HD 0.08838834764831845f

#define WC_QKV   ((size_t)DIM*DIM)
#define WC_MLP   ((size_t)MLPD*DIM)
#define WC_OUT   ((size_t)DIM*CATD)

// ---------------- scratch (device globals; no allocation allowed) ----------------
__device__ float  g_mod[2][3*DIM];
__device__ float  g_bias[2][3*DIM];
__device__ __half g_nh[2][SEQ*DIM];
__device__ __half g_qkv[6][SEQ*DIM];
__device__ __half g_sc[(size_t)72*SEQ*SEQ];     // scores; later reused as fp32 out-proj partials
__device__ __half g_hcat[2][SEQ*CATD];
__device__ __half g_wh[6*WC_QKV + WC_MLP + WC_OUT];
__device__ unsigned g_ctr[16];                  // per-launch tile queues (memset each replay)

// ---------------- helpers ----------------
__device__ __forceinline__ float gelu_t(float x){
  float u = 0.7978845608028654f*(x + 0.044715f*x*x*x);
  return 0.5f*x*(1.f + tanhf(u));
}
__device__ __forceinline__ void cpa16(const void* s, const void* g){
  unsigned sa = (unsigned)__cvta_generic_to_shared(s);
  asm volatile("cp.async.cg.shared.global [%0], [%1], 16;" :: "r"(sa), "l"(g));
}
__device__ __forceinline__ void cpcommit(){ asm volatile("cp.async.commit_group;"); }
template<int N> __device__ __forceinline__ void cpwait(){ asm volatile("cp.async.wait_group %0;"::"n"(N)); }
__device__ __forceinline__ void ldsm4(uint32_t& r0,uint32_t& r1,uint32_t& r2,uint32_t& r3,uint32_t addr){
  asm volatile("ldmatrix.sync.aligned.m8n8.x4.shared.b16 {%0,%1,%2,%3}, [%4];"
               : "=r"(r0),"=r"(r1),"=r"(r2),"=r"(r3) : "r"(addr));
}
__device__ __forceinline__ void ldsm4t(uint32_t& r0,uint32_t& r1,uint32_t& r2,uint32_t& r3,uint32_t addr){
  asm volatile("ldmatrix.sync.aligned.m8n8.x4.trans.shared.b16 {%0,%1,%2,%3}, [%4];"
               : "=r"(r0),"=r"(r1),"=r"(r2),"=r"(r3) : "r"(addr));
}
__device__ __forceinline__ void mma_h(float d[4], uint32_t A0,uint32_t A1,uint32_t A2,uint32_t A3,
                                      uint32_t B0,uint32_t B1){
  asm volatile("mma.sync.aligned.m16n8k16.row.col.f32.f16.f16.f32 "
               "{%0,%1,%2,%3},{%4,%5,%6,%7},{%8,%9},{%0,%1,%2,%3};"
               : "+f"(d[0]),"+f"(d[1]),"+f"(d[2]),"+f"(d[3])
               : "r"(A0),"r"(A1),"r"(A2),"r"(A3),"r"(B0),"r"(B1));
}

// ---------------- f32 -> f16 weight conversion ----------------
__global__ void cvt_h(const float* __restrict__ src, __half* __restrict__ dst, int n4){
  int i = blockIdx.x*blockDim.x + threadIdx.x;
  if (i < n4){
    float4 v = ((const float4*)src)[i];
    ((__half2*)dst)[2*i]   = __floats2half2_rn(v.x, v.y);
    ((__half2*)dst)[2*i+1] = __floats2half2_rn(v.z, v.w);
  }
}
__global__ void cvt6_h(const float* s0,const float* s1,const float* s2,
                       const float* s3,const float* s4,const float* s5,
                       __half* __restrict__ dst, int n4){
  const float* srcs[6] = {s0,s1,s2,s3,s4,s5};
  const float* src = srcs[blockIdx.y];
  __half* d = dst + (size_t)blockIdx.y*(size_t)n4*4;
  int i = blockIdx.x*blockDim.x + threadIdx.x;
  if (i < n4){
    float4 v = ((const float4*)src)[i];
    ((__half2*)d)[2*i]   = __floats2half2_rn(v.x, v.y);
    ((__half2*)d)[2*i+1] = __floats2half2_rn(v.z, v.w);
  }
}

// ---------------- pack q/k/v biases ----------------
__global__ void pack_bias_kernel(const float* __restrict__ qb, const float* __restrict__ kb,
                                 const float* __restrict__ vb, const float* __restrict__ qcb,
                                 const float* __restrict__ kcb, const float* __restrict__ vcb){
  int i = blockIdx.x*blockDim.x + threadIdx.x;
  if (i < DIM){
    g_bias[0][i] = qb[i];  g_bias[0][DIM+i] = kb[i];  g_bias[0][2*DIM+i] = vb[i];
    g_bias[1][i] = qcb[i]; g_bias[1][DIM+i] = kcb[i]; g_bias[1][2*DIM+i] = vcb[i];
  }
}

// ---------------- fused silu + modulation GEMV ----------------
__global__ void mod_gemv2(const float* __restrict__ w0, const float* __restrict__ b0,
                          const float* __restrict__ t0,
                          const float* __restrict__ w1, const float* __restrict__ b1,
                          const float* __restrict__ t1){
  __shared__ float ssil[DIM];
  const int stream = blockIdx.y;
  const float* w = stream ? w1 : w0;
  const float* b = stream ? b1 : b0;
  const float* t = stream ? t1 : t0;
  for (int i=threadIdx.x; i<DIM; i+=256){
    float x = t[i]; ssil[i] = x/(1.f+expf(-x));
  }
  __syncthreads();
  int warp = (blockIdx.x*blockDim.x + threadIdx.x) >> 5;
  int lane = threadIdx.x & 31;
  if (warp >= 3*DIM) return;
  const float4* wv = (const float4*)(w + (size_t)warp*DIM);
  const float4* sv = (const float4*)ssil;
  float acc = 0.f;
  for (int i = lane; i < DIM/4; i += 32){
    float4 a = wv[i], c = sv[i];
    acc += a.x*c.x + a.y*c.y + a.z*c.z + a.w*c.w;
  }
#pragma unroll
  for (int o=16;o;o>>=1) acc += __shfl_xor_sync(0xffffffffu, acc, o);
  if (!lane) g_mod[stream][warp] = acc + b[warp];
}

// ---------------- LayerNorm + modulate (half out) ----------------
__global__ void ln_mod2(const float* __restrict__ x0, const float* __restrict__ x1){
  __shared__ float sh[66];
  const int stream = blockIdx.y;
  const float* x = stream ? x1 : x0;
  int s = blockIdx.x;
  const float* row = x + (size_t)s*DIM;
  float sum=0.f, sq=0.f;
  for (int i=threadIdx.x; i<DIM; i+=256){ float v=row[i]; sum+=v; sq+=v*v; }
#pragma unroll
  for (int o=16;o;o>>=1){
    sum += __shfl_xor_sync(0xffffffffu,sum,o);
    sq  += __shfl_xor_sync(0xffffffffu,sq,o);
  }
  int w=threadIdx.x>>5, l=threadIdx.x&31;
  if (!l){ sh[w]=sum; sh[32+w]=sq; }
  __syncthreads();
  if (threadIdx.x==0){
    float a=0.f,b=0.f;
#pragma unroll
    for (int i=0;i<8;i++){ a+=sh[i]; b+=sh[32+i]; }
    sh[64]=a; sh[65]=b;
  }
  __syncthreads();
  float mu = sh[64]*(1.f/DIM);
  float var = sh[65]*(1.f/DIM) - mu*mu;
  float rstd = rsqrtf(var + 1e-6f);
  const float* shift = g_mod[stream];
  const float* scale = g_mod[stream] + DIM;
  __half* out = g_nh[stream] + (size_t)s*DIM;
  for (int i=threadIdx.x; i<DIM; i+=256)
    out[i] = __float2half_rn((row[i]-mu)*rstd*(1.f+scale[i]) + shift[i]);
}

// ---------------- per-(s,head) RMS + RoPE on half buffers ----------------
__global__ void rmsrope_kernel(__half* __restrict__ qkvbase,
                               const float* __restrict__ w0, const float* __restrict__ w1,
                               const float* __restrict__ w2, const float* __restrict__ w3,
                               const float* __restrict__ cosb, const float* __restrict__ sinb){
  const int bufsel[4] = {0,1,3,4};
  int b = blockIdx.y;
  __half* buf = qkvbase + (size_t)bufsel[b]*SEQ*DIM;
  const float* w = (b==0)?w0:(b==1)?w1:(b==2)?w2:w3;
  int idx  = blockIdx.x*blockDim.x + threadIdx.x;
  int warp = idx >> 5, lane = idx & 31;
  int s = warp / NHDS, h = warp % NHDS;
  uint2* row = (uint2*)(buf + (size_t)s*DIM + h*HD);
  uint2 raw = row[lane];
  __half2 p01 = *reinterpret_cast<__half2*>(&raw.x);
  __half2 p23 = *reinterpret_cast<__half2*>(&raw.y);
  float v0=__low2float(p01), v1=__high2float(p01);
  float v2=__low2float(p23), v3=__high2float(p23);
  float sq = v0*v0+v1*v1+v2*v2+v3*v3;
#pragma unroll
  for (int o=16;o;o>>=1) sq += __shfl_xor_sync(0xffffffffu, sq, o);
  float rstd = rsqrtf(sq*(1.f/HD) + 1e-6f);
  int d = lane*4;
  float4 wv = *(const float4*)(w + d);
  float4 cv = *(const float4*)(cosb + s*HD + d);
  float4 sv = *(const float4*)(sinb + s*HD + d);
  float x0=v0*rstd*wv.x, x1=v1*rstd*wv.y, x2=v2*rstd*wv.z, x3=v3*rstd*wv.w;
  float o0 = x0*cv.x - x1*sv.x;
  float o1 = x1*cv.y + x0*sv.y;
  float o2 = x2*cv.z - x3*sv.z;
  float o3 = x3*cv.w + x2*sv.w;
  __half2 q01 = __floats2half2_rn(o0,o1);
  __half2 q23 = __floats2half2_rn(o2,o3);
  raw.x = *reinterpret_cast<uint32_t*>(&q01);
  raw.y = *reinterpret_cast<uint32_t*>(&q23);
  row[lane] = raw;
}

// ---------------- row softmax on half scores (half2 vectorized) ----------------
__global__ void softmax_kernel(__half* __restrict__ p){
  __shared__ float sh[36];
  __half2* row = (__half2*)(p + (size_t)blockIdx.x*SEQ);
  int tid=threadIdx.x, w=tid>>5, l=tid&31;
  float m = -1e30f;
#pragma unroll
  for (int i=tid;i<SEQ/2;i+=256){
    __half2 v = row[i];
    m = fmaxf(m, fmaxf(__low2float(v), __high2float(v)));
  }
#pragma unroll
  for (int o=16;o;o>>=1) m = fmaxf(m, __shfl_xor_sync(0xffffffffu,m,o));
  if (!l) sh[w]=m;
  __syncthreads();
  if (tid==0){ float mm=sh[0]; for(int i=1;i<8;i++) mm=fmaxf(mm,sh[i]); sh[32]=mm; }
  __syncthreads();
  m = sh[32];
  float sum=0.f;
#pragma unroll
  for (int i=tid;i<SEQ/2;i+=256){
    __half2 v = row[i];
    float e0 = expf(__low2float(v)-m);
    float e1 = expf(__high2float(v)-m);
    row[i] = __floats2half2_rn(e0,e1);
    sum += e0+e1;
  }
#pragma unroll
  for (int o=16;o;o>>=1) sum += __shfl_xor_sync(0xffffffffu,sum,o);
  if (!l) sh[8+w]=sum;
  __syncthreads();
  if (tid==0){ float ss=0.f; for(int i=0;i<8;i++) ss+=sh[8+i]; sh[33]=ss; }
  __syncthreads();
  float inv = 1.f/sh[33];
#pragma unroll
  for (int i=tid;i<SEQ/2;i+=256){
    __half2 v = row[i];
    row[i] = __floats2half2_rn(__low2float(v)*inv, __high2float(v)*inv);
  }
}

// ---------------- combine out-proj partials: out = res + gate*(p_lo+p_hi+bias) ----------------
__global__ void combine_out(const float* __restrict__ parts, const float* __restrict__ outb,
                            const float* __restrict__ gates, const float* __restrict__ hs,
                            const float* __restrict__ hsc, float* __restrict__ out){
  const long long SD = (long long)SEQ*DIM;
  long long i4 = (long long)blockIdx.x*blockDim.x + threadIdx.x;
  if (i4 >= (2*SD)/4) return;
  long long i = i4*4;
  int stream = (i >= SD);
  long long li = i - (long long)stream*SD;
  int col = (int)(li % DIM);
  const float4 p1 = *(const float4*)(parts + (2*stream+0)*SD + li);
  const float4 p2 = *(const float4*)(parts + (2*stream+1)*SD + li);
  const float4 bb = *(const float4*)(outb + col);
  const float4 gg = *(const float4*)(gates + (size_t)stream*3*DIM + col);
  const float4 rr = *(const float4*)((stream ? hsc : hs) + li);
  float4 o;
  o.x = rr.x + gg.x*(p1.x+p2.x+bb.x);
  o.y = rr.y + gg.y*(p1.y+p2.y+bb.y);
  o.z = rr.z + gg.z*(p1.z+p2.z+bb.z);
  o.w = rr.w + gg.w*(p1.w+p2.w+bb.w);
  *(float4*)(out + i) = o;
}

// ================ persistent FP16 GEMM: dynamic tile queue, 3-stage pipeline ================
// BM=0: B [N,K] row-major (LDSM).  BM=1: B [K,N] row-major (LDSM.trans; PV).
// epi: 0=bias->half, 1=gelu(bias)->half, 2=*alpha->half, 3=acc+=Chalf->half, 5=raw float partial
#define AST   72
#define BST1  136
#define STG_H 18432
#define STG_B 36864
template<int BM>
__global__ __launch_bounds__(256,2) void gemm_h(
    const __half* __restrict__ Ab,  const __half* __restrict__ A2b, const __half* __restrict__ A3b,
    int lda, long long bsA,
    const __half* __restrict__ Bb,  const __half* __restrict__ B2b, const __half* __restrict__ B3b,
    int ldb, long long bsB,
    __half* __restrict__ Cb,  __half* __restrict__ C2b, __half* __restrict__ C3b,
    int ldc, long long bsC,
    float* __restrict__ Cfb, long long bsCf,
    int zs1, int zs2,
    int K,
    const float* __restrict__ biasb, int bsBias, int epi, float alpha,
    int gx, int gy, int numTiles, unsigned* __restrict__ ctr)
{
  extern __shared__ __half smh[];
  __shared__ int s_tile;
  const int tid = threadIdx.x;
  const int warp = tid>>5, lane = tid&31;
  const int wm = warp&1, wn = warp>>1;
  const int g = lane>>2, t = lane&3;
  const int j = lane>>3;

  const uint32_t smemBase = (uint32_t)__cvta_generic_to_shared(smh);
  const uint32_t aBase  = smemBase + (uint32_t)(((wm*64 + (j&1)*8 + (lane&7))*AST + (j>>1)*8)<<1);
  const uint32_t bBase0 = smemBase + (uint32_t)((9216 + (wn*32 + (j>>1)*8 + (lane&7))*AST + (j&1)*8)<<1);
  const uint32_t bBase1 = smemBase + (uint32_t)((9216 + ((j&1)*8 + (lane&7))*BST1 + wn*32 + (j>>1)*8)<<1);
  const int KT = K >> 6;

  for (;;){
    if (tid==0) s_tile = (int)atomicAdd(ctr, 1u);
    __syncthreads();                // also fences prior tile's smem reads vs new writes
    const int tile = s_tile;
    if (tile >= numTiles) break;
    const int bx = tile % gx;
    const int t2 = tile / gx;
    const int by = t2 % gy;
    const int z  = t2 / gy;

    const __half *A, *B; __half *C;
    {
      long long zo;
      if (z < zs1){ A=Ab;  B=Bb;  C=Cb;  zo=z; }
      else if (z < zs2){ A=A2b; B=B2b; C=C2b; zo=z-zs1; }
      else { A=A3b; B=B3b; C=C3b; zo=z-zs2; }
      A += zo*bsA; B += zo*bsB; C += zo*bsC;
    }
    float* Cf = Cfb ? Cfb + (long long)z*bsCf : nullptr;
    const float* bias = biasb ? biasb + (long long)z*bsBias : nullptr;
    const int bm0 = by*128, bn0 = bx*128;

    auto load_tile = [&](int kt, int buf){
      __half* As = smh + buf*STG_H;
      __half* Bs = As + 9216;
      const int k0 = kt<<6;
      {
        const int c8=(tid&7)*8, r=tid>>3;
#pragma unroll
        for (int it=0; it<4; it++){
          int row=r+it*32;
          cpa16(As + row*AST + c8, A + (long long)(bm0+row)*lda + (k0+c8));
        }
      }
      if (BM==0){
        const int c8=(tid&7)*8, r=tid>>3;
#pragma unroll
        for (int it=0; it<4; it++){
          int row=r+it*32;
          cpa16(Bs + row*AST + c8, B + (long long)(bn0+row)*ldb + (k0+c8));
        }
      } else {
        const int n8=(tid&15)*8, r=tid>>4;
#pragma unroll
        for (int it=0; it<4; it++){
          int kk=r+it*16;
          cpa16(Bs + kk*BST1 + n8, B + (long long)(k0+kk)*ldb + (bn0+n8));
        }
      }
    };

    float acc[4][4][4];
#pragma unroll
    for (int a=0;a<4;a++)
#pragma unroll
      for (int b=0;b<4;b++)
#pragma unroll
        for (int c=0;c<4;c++) acc[a][b][c]=0.f;

    load_tile(0,0); cpcommit();
    if (KT > 1){ load_tile(1,1); cpcommit(); }
    int cur = 0, nxt = 2;

    for (int kt=0; kt<KT; kt++){
      if (kt+1 < KT) cpwait<1>(); else cpwait<0>();
      __syncthreads();
      if (kt+2 < KT){
        load_tile(kt+2, nxt); cpcommit();
        nxt = (nxt==2)?0:nxt+1;
      }
      const uint32_t stByte = cur*STG_B;

#pragma unroll
      for (int kk=0; kk<4; kk++){
        const uint32_t kByte = stByte + kk*32;
        uint32_t a[4][4];
#pragma unroll
        for (int mt=0; mt<4; mt++)
          ldsm4(a[mt][0],a[mt][1],a[mt][2],a[mt][3], aBase + mt*2304u + kByte);

        uint32_t b0[4], b1[4];
        if (BM==0){
#pragma unroll
          for (int p=0; p<2; p++){
            uint32_t r0,r1,r2,r3;
            ldsm4(r0,r1,r2,r3, bBase0 + p*2304u + kByte);
            b0[2*p]=r0; b1[2*p]=r1; b0[2*p+1]=r2; b1[2*p+1]=r3;
          }
        } else {
#pragma unroll
          for (int p=0; p<2; p++){
            uint32_t r0,r1,r2,r3;
            ldsm4t(r0,r1,r2,r3, bBase1 + p*32u + (stByte + kk*4352u));
            b0[2*p]=r0; b1[2*p]=r1; b0[2*p+1]=r2; b1[2*p+1]=r3;
          }
        }
#pragma unroll
        for (int mt=0; mt<4; mt++)
#pragma unroll
          for (int nt=0; nt<4; nt++)
            mma_h(acc[mt][nt], a[mt][0],a[mt][1],a[mt][2],a[mt][3], b0[nt],b1[nt]);
      }
      cur = (cur==2)?0:cur+1;
    }

#pragma unroll
    for (int mt=0; mt<4; mt++){
#pragma unroll
      for (int nt=0; nt<4; nt++){
#pragma unroll
        for (int i=0; i<4; i++){
          int row = bm0 + wm*64 + mt*16 + g + ((i&2)?8:0);
          int col = bn0 + wn*32 + nt*8 + t*2 + (i&1);
          long long idx = (long long)row*ldc + col;
          float v = acc[mt][nt][i];
          if (bias) v += bias[col];
          if (epi==0)      C[idx] = __float2half_rn(v);
          else if (epi==1) C[idx] = __float2half_rn(gelu_t(v));
          else if (epi==2) C[idx] = __float2half_rn(v*alpha);
          else if (epi==3) C[idx] = __float2half_rn(v + __half2float(C[idx]));
          else             Cf[idx] = v;
        }
      }
    }
  }
}

// ---------------- host orchestration ----------------
struct GArgs {
  const __half *A,*A2,*A3; int lda; long long bsA;
  const __half *B,*B2,*B3; int ldb; long long bsB; int bmode;
  __half *C,*C2,*C3; int ldc; long long bsC;
  float* Cf; long long bsCf;
  int zs1, zs2, M, N, K, batch;
  const float* bias; int bsBias; int epi; float alpha;
  unsigned* ctr;
};
static void launch_g(const GArgs& a){
  int gx = a.N/128, gy = a.M/128;
  int numTiles = gx*gy*a.batch;
  int grid = numTiles < 592 ? numTiles : 592;
  size_t shm = STG_B*3;
#define GCALL(BM) gemm_h<BM><<<grid,256,shm>>>( \
      a.A,a.A2,a.A3,a.lda,a.bsA, a.B,a.B2,a.B3,a.ldb,a.bsB, \
      a.C,a.C2,a.C3,a.ldc,a.bsC, a.Cf,a.bsCf, a.zs1,a.zs2, a.K, \
      a.bias,a.bsBias,a.epi,a.alpha, gx,gy,numTiles,a.ctr)
  if (a.bmode==0) GCALL(0); else GCALL(1);
#undef GCALL
}

extern "C" void kernel_launch(void* const* d_in, const int* in_sizes, int n_in,
                              void* d_out, int out_size){
  const float* hs     = (const float*)d_in[0];
  const float* temb   = (const float*)d_in[1];
  const float* hsc    = (const float*)d_in[2];
  const float* tembc  = (const float*)d_in[3];
  const float* ropec  = (const float*)d_in[4];
  const float* ropes  = (const float*)d_in[5];
  const float* norm_w = (const float*)d_in[6];
  const float* norm_b = (const float*)d_in[7];
  const float* normc_w= (const float*)d_in[8];
  const float* normc_b= (const float*)d_in[9];
  const float* mlp_w  = (const float*)d_in[10];
  const float* mlp_b  = (const float*)d_in[11];
  const float* out_w  = (const float*)d_in[12];
  const float* out_b  = (const float*)d_in[13];
  const float* q_w    = (const float*)d_in[14];
  const float* q_b    = (const float*)d_in[15];
  const float* k_w    = (const float*)d_in[16];
  const float* k_b    = (const float*)d_in[17];
  const float* v_w    = (const float*)d_in[18];
  const float* v_b    = (const float*)d_in[19];
  const float* rms_q  = (const float*)d_in[20];
  const float* rms_k  = (const float*)d_in[21];
  const float* qc_w   = (const float*)d_in[22];
  const float* qc_b   = (const float*)d_in[23];
  const float* kc_w   = (const float*)d_in[24];
  const float* kc_b   = (const float*)d_in[25];
  const float* vc_w   = (const float*)d_in[26];
  const float* vc_b   = (const float*)d_in[27];
  const float* rms_qc = (const float*)d_in[28];
  const float* rms_kc = (const float*)d_in[29];
  float* out = (float*)d_out;

  static __half *p_nh=nullptr, *p_qkv=nullptr, *p_sc=nullptr, *p_hc=nullptr, *p_wh=nullptr;
  static float *p_mod=nullptr, *p_bias=nullptr;
  static unsigned* p_ctr=nullptr;
  if (!p_nh){
    cudaGetSymbolAddress((void**)&p_nh,  g_nh);
    cudaGetSymbolAddress((void**)&p_qkv, g_qkv);
    cudaGetSymbolAddress((void**)&p_sc,  g_sc);
    cudaGetSymbolAddress((void**)&p_hc,  g_hcat);
    cudaGetSymbolAddress((void**)&p_wh,  g_wh);
    cudaGetSymbolAddress((void**)&p_mod, g_mod);
    cudaGetSymbolAddress((void**)&p_bias,g_bias);
    cudaGetSymbolAddress((void**)&p_ctr, g_ctr);
    cudaFuncSetAttribute(gemm_h<0>, cudaFuncAttributeMaxDynamicSharedMemorySize, STG_B*3);
    cudaFuncSetAttribute(gemm_h<1>, cudaFuncAttributeMaxDynamicSharedMemorySize, STG_B*3);
  }
  const size_t SD = (size_t)SEQ*DIM;
  __half* nh0 = p_nh;          __half* nh1 = p_nh + SD;
  __half* q   = p_qkv + 0*SD;  __half* kb_ = p_qkv + 1*SD;  __half* v   = p_qkv + 2*SD;
  __half* qc  = p_qkv + 3*SD;  __half* kc  = p_qkv + 4*SD;  __half* vc  = p_qkv + 5*SD;
  __half* hcat0 = p_hc;        __half* hcat1 = p_hc + (size_t)SEQ*CATD;
  float* gate0 = p_mod + 2*DIM;
  const long long SS = (long long)SEQ*SEQ;
  __half* sc_ctrl  = p_sc + 24*SS;
  __half* sc_cross = p_sc + 48*SS;
  float* parts = (float*)p_sc;            // reuse score scratch for out-proj fp32 partials

  __half* wh_q  = p_wh + 0*WC_QKV;
  __half* wh_k  = p_wh + 1*WC_QKV;
  __half* wh_v  = p_wh + 2*WC_QKV;
  __half* wh_qc = p_wh + 3*WC_QKV;
  __half* wh_kc = p_wh + 4*WC_QKV;
  __half* wh_vc = p_wh + 5*WC_QKV;
  __half* wh_ml = p_wh + 6*WC_QKV;
  __half* wh_ou = p_wh + 6*WC_QKV + WC_MLP;

  // 0: reset tile-queue counters (replayed each graph launch)
  cudaMemsetAsync(p_ctr, 0, 16*sizeof(unsigned));
  // 1: mlp weight cvt
  { int n4 = (int)(WC_MLP/4); cvt_h<<<(n4+255)/256,256>>>(mlp_w, wh_ml, n4); }
  // 2: modulation
  { dim3 grid((3*DIM)/8, 2); mod_gemv2<<<grid,256>>>(norm_w,norm_b,temb, normc_w,normc_b,tembc); }
  // 3: layernorm+modulate
  { dim3 grid(SEQ,2); ln_mod2<<<grid,256>>>(hs, hsc); }
  // 4: MLP both streams, z=2
  { GArgs a{};
    a.A=nh0; a.A2=a.A3=nh0; a.lda=DIM; a.bsA=(long long)SD;
    a.B=wh_ml; a.B2=a.B3=wh_ml; a.ldb=DIM; a.bsB=0; a.bmode=0;
    a.C=hcat0+DIM; a.C2=a.C3=a.C; a.ldc=CATD; a.bsC=(long long)SEQ*CATD;
    a.Cf=nullptr; a.bsCf=0;
    a.zs1=2; a.zs2=2; a.M=SEQ; a.N=MLPD; a.K=DIM; a.batch=2;
    a.bias=mlp_b; a.bsBias=0; a.epi=1; a.alpha=0.f; a.ctr=p_ctr+0;
    launch_g(a); }
  // 5: qkv weight cvts
  { int n4 = (int)(WC_QKV/4); dim3 grid((n4+255)/256, 6);
    cvt6_h<<<grid,256>>>(q_w,k_w,v_w,qc_w,kc_w,vc_w, p_wh, n4); }
  // 6: out weight cvt
  { int n4 = (int)(WC_OUT/4); cvt_h<<<(n4+255)/256,256>>>(out_w, wh_ou, n4); }
  // 7: bias pack
  pack_bias_kernel<<<(DIM+255)/256,256>>>(q_b,k_b,v_b,qc_b,kc_b,vc_b);
  // 8,9: QKV projections z=3 per stream
  { GArgs a{};
    a.A=nh0; a.A2=a.A3=nh0; a.lda=DIM; a.bsA=0;
    a.B=wh_q; a.B2=wh_k; a.B3=wh_v; a.ldb=DIM; a.bsB=0; a.bmode=0;
    a.C=q; a.C2=kb_; a.C3=v; a.ldc=DIM; a.bsC=0;
    a.Cf=nullptr; a.bsCf=0;
    a.zs1=1; a.zs2=2; a.M=SEQ; a.N=DIM; a.K=DIM; a.batch=3;
    a.bias=p_bias; a.bsBias=DIM; a.epi=0; a.alpha=0.f; a.ctr=p_ctr+1;
    launch_g(a); }
  { GArgs a{};
    a.A=nh1; a.A2=a.A3=nh1; a.lda=DIM; a.bsA=0;
    a.B=wh_qc; a.B2=wh_kc; a.B3=wh_vc; a.ldb=DIM; a.bsB=0; a.bmode=0;
    a.C=qc; a.C2=kc; a.C3=vc; a.ldc=DIM; a.bsC=0;
    a.Cf=nullptr; a.bsCf=0;
    a.zs1=1; a.zs2=2; a.M=SEQ; a.N=DIM; a.K=DIM; a.batch=3;
    a.bias=p_bias+3*DIM; a.bsBias=DIM; a.epi=0; a.alpha=0.f; a.ctr=p_ctr+2;
    launch_g(a); }
  // 10: RMS + RoPE (q,k,qc,kc)
  { dim3 grid(3072,4); rmsrope_kernel<<<grid,256>>>(p_qkv, rms_q, rms_k, rms_qc, rms_kc, ropec, ropes); }
  // 11: QK^T main+ctrl+cross, z=72
  { GArgs a{};
    a.A=q;  a.A2=qc; a.A3=q;  a.lda=DIM; a.bsA=HD;
    a.B=kb_; a.B2=kc; a.B3=kc; a.ldb=DIM; a.bsB=HD; a.bmode=0;
    a.C=p_sc; a.C2=sc_ctrl; a.C3=sc_cross; a.ldc=SEQ; a.bsC=SS;
    a.Cf=nullptr; a.bsCf=0;
    a.zs1=24; a.zs2=48; a.M=SEQ; a.N=SEQ; a.K=HD; a.batch=72;
    a.bias=nullptr; a.bsBias=0; a.epi=2; a.alpha=INV_SQRT_HD; a.ctr=p_ctr+3;
    launch_g(a); }
  // 12: softmax 72K rows
  softmax_kernel<<<72*SEQ,256>>>(p_sc);
  // 13: PV main+ctrl, z=48 (BM=1)
  { GArgs a{};
    a.A=p_sc; a.A2=sc_ctrl; a.A3=sc_ctrl; a.lda=SEQ; a.bsA=SS;
    a.B=v; a.B2=vc; a.B3=vc; a.ldb=DIM; a.bsB=HD; a.bmode=1;
    a.C=hcat0; a.C2=hcat1; a.C3=hcat1; a.ldc=CATD; a.bsC=HD;
    a.Cf=nullptr; a.bsCf=0;
    a.zs1=24; a.zs2=48; a.M=SEQ; a.N=HD; a.K=SEQ; a.batch=48;
    a.bias=nullptr; a.bsBias=0; a.epi=0; a.alpha=0.f; a.ctr=p_ctr+4;
    launch_g(a); }
  // 14: PV cross, accumulate into hcat0 (BM=1)
  { GArgs a{};
    a.A=sc_cross; a.A2=sc_cross; a.A3=sc_cross; a.lda=SEQ; a.bsA=SS;
    a.B=vc; a.B2=vc; a.B3=vc; a.ldb=DIM; a.bsB=HD; a.bmode=1;
    a.C=hcat0; a.C2=hcat0; a.C3=hcat0; a.ldc=CATD; a.bsC=HD;
    a.Cf=nullptr; a.bsCf=0;
    a.zs1=24; a.zs2=24; a.M=SEQ; a.N=HD; a.K=SEQ; a.batch=24;
    a.bias=nullptr; a.bsBias=0; a.epi=3; a.alpha=0.f; a.ctr=p_ctr+5;
    launch_g(a); }
  // 15: output projection split-K, z=4 -> fp32 partials in score scratch
  { GArgs a{};
    a.A=hcat0; a.A2=hcat0+KHALF; a.A3=hcat1; a.lda=CATD; a.bsA=KHALF;
    a.B=wh_ou; a.B2=wh_ou+KHALF; a.B3=wh_ou; a.ldb=CATD; a.bsB=KHALF; a.bmode=0;
    a.C=nullptr; a.C2=a.C3=nullptr; a.ldc=DIM; a.bsC=0;
    a.Cf=parts; a.bsCf=(long long)SD;
    a.zs1=1; a.zs2=2; a.M=SEQ; a.N=DIM; a.K=KHALF; a.batch=4;
    a.bias=nullptr; a.bsBias=0; a.epi=5; a.alpha=0.f; a.ctr=p_ctr+6;
    launch_g(a); }
  // 16: combine partials + bias + gate + residual -> out
  { long long n4 = (2*(long long)SD)/4;
    combine_out<<<(unsigned)((n4+255)/256),256>>>(parts, out_b, gate0, hs, hsc, out); }
}

// round 15
// speedup vs baseline: 1.0108x; 1.0108x over previous
#include <cuda_runtime.h>
#include <cuda_fp16.h>
#include <math.h>
#include <stdint.h>

#define SEQ   1024
#define DIM   3072
#define NHDS  24
#define HD    128
#define MLPD  12288
#define CATD  15360
#define KHALF 7680
#define INV_SQRT_HD 0.08838834764831845f

#define WC_QKV   ((size_t)DIM*DIM)
#define WC_MLP   ((size_t)MLPD*DIM)
#define WC_OUT   ((size_t)DIM*CATD)

// ---------------- scratch (device globals; no allocation allowed) ----------------
__device__ float  g_mod[2][3*DIM];
__device__ float  g_bias[2][3*DIM];
__device__ __half g_nh[2][SEQ*DIM];
__device__ __half g_qkv[6][SEQ*DIM];            // q,k,v,qc,kc,vc
__device__ __half g_sc[(size_t)72*SEQ*SEQ];     // scores; later reused as fp32 out-proj partials
__device__ __half g_hcat[2][SEQ*CATD];
__device__ __half g_wh[6*WC_QKV + WC_MLP + WC_OUT];

// ---------------- helpers ----------------
__device__ __forceinline__ float gelu_t(float x){
  float u = 0.7978845608028654f*(x + 0.044715f*x*x*x);
  return 0.5f*x*(1.f + tanhf(u));
}
__device__ __forceinline__ void cpa16(const void* s, const void* g){
  unsigned sa = (unsigned)__cvta_generic_to_shared(s);
  asm volatile("cp.async.cg.shared.global [%0], [%1], 16;" :: "r"(sa), "l"(g));
}
__device__ __forceinline__ void cpcommit(){ asm volatile("cp.async.commit_group;"); }
template<int N> __device__ __forceinline__ void cpwait(){ asm volatile("cp.async.wait_group %0;"::"n"(N)); }
__device__ __forceinline__ void ldsm4(uint32_t& r0,uint32_t& r1,uint32_t& r2,uint32_t& r3,uint32_t addr){
  asm volatile("ldmatrix.sync.aligned.m8n8.x4.shared.b16 {%0,%1,%2,%3}, [%4];"
               : "=r"(r0),"=r"(r1),"=r"(r2),"=r"(r3) : "r"(addr));
}
__device__ __forceinline__ void ldsm4t(uint32_t& r0,uint32_t& r1,uint32_t& r2,uint32_t& r3,uint32_t addr){
  asm volatile("ldmatrix.sync.aligned.m8n8.x4.trans.shared.b16 {%0,%1,%2,%3}, [%4];"
               : "=r"(r0),"=r"(r1),"=r"(r2),"=r"(r3) : "r"(addr));
}
__device__ __forceinline__ void mma_h(float d[4], uint32_t A0,uint32_t A1,uint32_t A2,uint32_t A3,
                                      uint32_t B0,uint32_t B1){
  asm volatile("mma.sync.aligned.m16n8k16.row.col.f32.f16.f16.f32 "
               "{%0,%1,%2,%3},{%4,%5,%6,%7},{%8,%9},{%0,%1,%2,%3};"
               : "+f"(d[0]),"+f"(d[1]),"+f"(d[2]),"+f"(d[3])
               : "r"(A0),"r"(A1),"r"(A2),"r"(A3),"r"(B0),"r"(B1));
}

// ---------------- f32 -> f16 weight conversion ----------------
__global__ void cvt_h(const float* __restrict__ src, __half* __restrict__ dst, int n4){
  int i = blockIdx.x*blockDim.x + threadIdx.x;
  if (i < n4){
    float4 v = ((const float4*)src)[i];
    ((__half2*)dst)[2*i]   = __floats2half2_rn(v.x, v.y);
    ((__half2*)dst)[2*i+1] = __floats2half2_rn(v.z, v.w);
  }
}
__global__ void cvt6_h(const float* s0,const float* s1,const float* s2,
                       const float* s3,const float* s4,const float* s5,
                       __half* __restrict__ dst, int n4){
  const float* srcs[6] = {s0,s1,s2,s3,s4,s5};
  const float* src = srcs[blockIdx.y];
  __half* d = dst + (size_t)blockIdx.y*(size_t)n4*4;
  int i = blockIdx.x*blockDim.x + threadIdx.x;
  if (i < n4){
    float4 v = ((const float4*)src)[i];
    ((__half2*)d)[2*i]   = __floats2half2_rn(v.x, v.y);
    ((__half2*)d)[2*i+1] = __floats2half2_rn(v.z, v.w);
  }
}

// ---------------- pack q/k/v biases ----------------
__global__ void pack_bias_kernel(const float* __restrict__ qb, const float* __restrict__ kb,
                                 const float* __restrict__ vb, const float* __restrict__ qcb,
                                 const float* __restrict__ kcb, const float* __restrict__ vcb){
  int i = blockIdx.x*blockDim.x + threadIdx.x;
  if (i < DIM){
    g_bias[0][i] = qb[i];  g_bias[0][DIM+i] = kb[i];  g_bias[0][2*DIM+i] = vb[i];
    g_bias[1][i] = qcb[i]; g_bias[1][DIM+i] = kcb[i]; g_bias[1][2*DIM+i] = vcb[i];
  }
}

// ---------------- fused silu + modulation GEMV ----------------
__global__ void mod_gemv2(const float* __restrict__ w0, const float* __restrict__ b0,
                          const float* __restrict__ t0,
                          const float* __restrict__ w1, const float* __restrict__ b1,
                          const float* __restrict__ t1){
  __shared__ float ssil[DIM];
  const int stream = blockIdx.y;
  const float* w = stream ? w1 : w0;
  const float* b = stream ? b1 : b0;
  const float* t = stream ? t1 : t0;
  for (int i=threadIdx.x; i<DIM; i+=256){
    float x = t[i]; ssil[i] = x/(1.f+expf(-x));
  }
  __syncthreads();
  int warp = (blockIdx.x*blockDim.x + threadIdx.x) >> 5;
  int lane = threadIdx.x & 31;
  if (warp >= 3*DIM) return;
  const float4* wv = (const float4*)(w + (size_t)warp*DIM);
  const float4* sv = (const float4*)ssil;
  float acc = 0.f;
  for (int i = lane; i < DIM/4; i += 32){
    float4 a = wv[i], c = sv[i];
    acc += a.x*c.x + a.y*c.y + a.z*c.z + a.w*c.w;
  }
#pragma unroll
  for (int o=16;o;o>>=1) acc += __shfl_xor_sync(0xffffffffu, acc, o);
  if (!lane) g_mod[stream][warp] = acc + b[warp];
}

// ---------------- LayerNorm + modulate (half out) ----------------
__global__ void ln_mod2(const float* __restrict__ x0, const float* __restrict__ x1){
  __shared__ float sh[66];
  const int stream = blockIdx.y;
  const float* x = stream ? x1 : x0;
  int s = blockIdx.x;
  const float* row = x + (size_t)s*DIM;
  float sum=0.f, sq=0.f;
  for (int i=threadIdx.x; i<DIM; i+=256){ float v=row[i]; sum+=v; sq+=v*v; }
#pragma unroll
  for (int o=16;o;o>>=1){
    sum += __shfl_xor_sync(0xffffffffu,sum,o);
    sq  += __shfl_xor_sync(0xffffffffu,sq,o);
  }
  int w=threadIdx.x>>5, l=threadIdx.x&31;
  if (!l){ sh[w]=sum; sh[32+w]=sq; }
  __syncthreads();
  if (threadIdx.x==0){
    float a=0.f,b=0.f;
#pragma unroll
    for (int i=0;i<8;i++){ a+=sh[i]; b+=sh[32+i]; }
    sh[64]=a; sh[65]=b;
  }
  __syncthreads();
  float mu = sh[64]*(1.f/DIM);
  float var = sh[65]*(1.f/DIM) - mu*mu;
  float rstd = rsqrtf(var + 1e-6f);
  const float* shift = g_mod[stream];
  const float* scale = g_mod[stream] + DIM;
  __half* out = g_nh[stream] + (size_t)s*DIM;
  for (int i=threadIdx.x; i<DIM; i+=256)
    out[i] = __float2half_rn((row[i]-mu)*rstd*(1.f+scale[i]) + shift[i]);
}

// ---------------- per-(s,head) RMS + RoPE on half buffers ----------------
__global__ void rmsrope_kernel(__half* __restrict__ qkvbase,
                               const float* __restrict__ w0, const float* __restrict__ w1,
                               const float* __restrict__ w2, const float* __restrict__ w3,
                               const float* __restrict__ cosb, const float* __restrict__ sinb){
  const int bufsel[4] = {0,1,3,4};
  int b = blockIdx.y;
  __half* buf = qkvbase + (size_t)bufsel[b]*SEQ*DIM;
  const float* w = (b==0)?w0:(b==1)?w1:(b==2)?w2:w3;
  int idx  = blockIdx.x*blockDim.x + threadIdx.x;
  int warp = idx >> 5, lane = idx & 31;
  int s = warp / NHDS, h = warp % NHDS;
  uint2* row = (uint2*)(buf + (size_t)s*DIM + h*HD);
  uint2 raw = row[lane];
  __half2 p01 = *reinterpret_cast<__half2*>(&raw.x);
  __half2 p23 = *reinterpret_cast<__half2*>(&raw.y);
  float v0=__low2float(p01), v1=__high2float(p01);
  float v2=__low2float(p23), v3=__high2float(p23);
  float sq = v0*v0+v1*v1+v2*v2+v3*v3;
#pragma unroll
  for (int o=16;o;o>>=1) sq += __shfl_xor_sync(0xffffffffu, sq, o);
  float rstd = rsqrtf(sq*(1.f/HD) + 1e-6f);
  int d = lane*4;
  float4 wv = *(const float4*)(w + d);
  float4 cv = *(const float4*)(cosb + s*HD + d);
  float4 sv = *(const float4*)(sinb + s*HD + d);
  float x0=v0*rstd*wv.x, x1=v1*rstd*wv.y, x2=v2*rstd*wv.z, x3=v3*rstd*wv.w;
  float o0 = x0*cv.x - x1*sv.x;
  float o1 = x1*cv.y + x0*sv.y;
  float o2 = x2*cv.z - x3*sv.z;
  float o3 = x3*cv.w + x2*sv.w;
  __half2 q01 = __floats2half2_rn(o0,o1);
  __half2 q23 = __floats2half2_rn(o2,o3);
  raw.x = *reinterpret_cast<uint32_t*>(&q01);
  raw.y = *reinterpret_cast<uint32_t*>(&q23);
  row[lane] = raw;
}

// ---------------- row softmax on half scores (half2 vectorized) ----------------
__global__ void softmax_kernel(__half* __restrict__ p){
  __shared__ float sh[36];
  __half2* row = (__half2*)(p + (size_t)blockIdx.x*SEQ);
  int tid=threadIdx.x, w=tid>>5, l=tid&31;
  float m = -1e30f;
#pragma unroll
  for (int i=tid;i<SEQ/2;i+=256){
    __half2 v = row[i];
    m = fmaxf(m, fmaxf(__low2float(v), __high2float(v)));
  }
#pragma unroll
  for (int o=16;o;o>>=1) m = fmaxf(m, __shfl_xor_sync(0xffffffffu,m,o));
  if (!l) sh[w]=m;
  __syncthreads();
  if (tid==0){ float mm=sh[0]; for(int i=1;i<8;i++) mm=fmaxf(mm,sh[i]); sh[32]=mm; }
  __syncthreads();
  m = sh[32];
  float sum=0.f;
#pragma unroll
  for (int i=tid;i<SEQ/2;i+=256){
    __half2 v = row[i];
    float e0 = expf(__low2float(v)-m);
    float e1 = expf(__high2float(v)-m);
    row[i] = __floats2half2_rn(e0,e1);
    sum += e0+e1;
  }
#pragma unroll
  for (int o=16;o;o>>=1) sum += __shfl_xor_sync(0xffffffffu,sum,o);
  if (!l) sh[8+w]=sum;
  __syncthreads();
  if (tid==0){ float ss=0.f; for(int i=0;i<8;i++) ss+=sh[8+i]; sh[33]=ss; }
  __syncthreads();
  float inv = 1.f/sh[33];
#pragma unroll
  for (int i=tid;i<SEQ/2;i+=256){
    __half2 v = row[i];
    row[i] = __floats2half2_rn(__low2float(v)*inv, __high2float(v)*inv);
  }
}

// ---------------- combine out-proj partials: out = res + gate*(p_lo+p_hi+bias) ----------------
__global__ void combine_out(const float* __restrict__ parts, const float* __restrict__ outb,
                            const float* __restrict__ gates, const float* __restrict__ hs,
                            const float* __restrict__ hsc, float* __restrict__ out){
  const long long SD = (long long)SEQ*DIM;
  long long i4 = (long long)blockIdx.x*blockDim.x + threadIdx.x;
  if (i4 >= (2*SD)/4) return;
  long long i = i4*4;
  int stream = (i >= SD);
  long long li = i - (long long)stream*SD;
  int col = (int)(li % DIM);
  const float4 p1 = *(const float4*)(parts + (2*stream+0)*SD + li);
  const float4 p2 = *(const float4*)(parts + (2*stream+1)*SD + li);
  const float4 bb = *(const float4*)(outb + col);
  const float4 gg = *(const float4*)(gates + (size_t)stream*3*DIM + col);
  const float4 rr = *(const float4*)((stream ? hsc : hs) + li);
  float4 o;
  o.x = rr.x + gg.x*(p1.x+p2.x+bb.x);
  o.y = rr.y + gg.y*(p1.y+p2.y+bb.y);
  o.z = rr.z + gg.z*(p1.z+p2.z+bb.z);
  o.w = rr.w + gg.w*(p1.w+p2.w+bb.w);
  *(float4*)(out + i) = o;
}

// ================ 3-stage pipelined FP16 GEMM (m16n8k16, fp32 acc) ================
// BM=0: B [N,K] row-major (LDSM).  BM=1: B [K,N] row-major (LDSM.trans; PV).
// epi: 0=bias->half, 1=gelu(bias)->half, 2=*alpha->half, 3=acc+=Chalf->half, 5=raw float partial
#define AST   72
#define BST1  136
#define STG_H 18432
#define STG_B 36864
template<int BM>
__global__ __launch_bounds__(256,2) void gemm_h(
    const __half* __restrict__ A,  const __half* __restrict__ A2, const __half* __restrict__ A3,
    int lda, long long bsA,
    const __half* __restrict__ B,  const __half* __restrict__ B2, const __half* __restrict__ B3,
    int ldb, long long bsB,
    __half* __restrict__ C,  __half* __restrict__ C2, __half* __restrict__ C3,
    int ldc, long long bsC,
    float* __restrict__ Cf, long long bsCf,
    int zs1, int zs2,
    int K,
    const float* __restrict__ bias, int bsBias, int epi, float alpha)
{
  extern __shared__ __half smh[];
  const int z = blockIdx.z;
  {
    long long zo;
    if (z < zs1){ zo = z; }
    else if (z < zs2){ A = A2; B = B2; C = C2; zo = z - zs1; }
    else { A = A3; B = B3; C = C3; zo = z - zs2; }
    A += zo*bsA;  B += zo*bsB;  C += zo*bsC;
  }
  if (Cf) Cf += (long long)z*bsCf;
  if (bias) bias += (long long)z*bsBias;
  const int bm0 = blockIdx.y*128, bn0 = blockIdx.x*128;
  const int tid = threadIdx.x;
  const int warp = tid>>5, lane = tid&31;
  const int wm = warp&1, wn = warp>>1;
  const int g = lane>>2, t = lane&3;
  const int j = lane>>3;

  const uint32_t smemBase = (uint32_t)__cvta_generic_to_shared(smh);
  const uint32_t aBase  = smemBase + (uint32_t)(((wm*64 + (j&1)*8 + (lane&7))*AST + (j>>1)*8)<<1);
  const uint32_t bBase0 = smemBase + (uint32_t)((9216 + (wn*32 + (j>>1)*8 + (lane&7))*AST + (j&1)*8)<<1);
  const uint32_t bBase1 = smemBase + (uint32_t)((9216 + ((j&1)*8 + (lane&7))*BST1 + wn*32 + (j>>1)*8)<<1);

  auto load_tile = [&](int kt, int buf){
    __half* As = smh + buf*STG_H;
    __half* Bs = As + 9216;
    const int k0 = kt<<6;
    {
      const int c8=(tid&7)*8, r=tid>>3;
#pragma unroll
      for (int it=0; it<4; it++){
        int row=r+it*32;
        cpa16(As + row*AST + c8, A + (long long)(bm0+row)*lda + (k0+c8));
      }
    }
    if (BM==0){
      const int c8=(tid&7)*8, r=tid>>3;
#pragma unroll
      for (int it=0; it<4; it++){
        int row=r+it*32;
        cpa16(Bs + row*AST + c8, B + (long long)(bn0+row)*ldb + (k0+c8));
      }
    } else {
      const int n8=(tid&15)*8, r=tid>>4;
#pragma unroll
      for (int it=0; it<4; it++){
        int kk=r+it*16;
        cpa16(Bs + kk*BST1 + n8, B + (long long)(k0+kk)*ldb + (bn0+n8));
      }
    }
  };

  float acc[4][4][4];
#pragma unroll
  for (int a=0;a<4;a++)
#pragma unroll
    for (int b=0;b<4;b++)
#pragma unroll
      for (int c=0;c<4;c++) acc[a][b][c]=0.f;

  const int KT = K >> 6;
  load_tile(0,0); cpcommit();
  if (KT > 1){ load_tile(1,1); cpcommit(); }
  int cur = 0, nxt = 2;

  for (int kt=0; kt<KT; kt++){
    if (kt+1 < KT) cpwait<1>(); else cpwait<0>();
    __syncthreads();
    if (kt+2 < KT){
      load_tile(kt+2, nxt); cpcommit();
      nxt = (nxt==2)?0:nxt+1;
    }
    const uint32_t stByte = cur*STG_B;

#pragma unroll
    for (int kk=0; kk<4; kk++){
      const uint32_t kByte = stByte + kk*32;
      uint32_t a[4][4];
#pragma unroll
      for (int mt=0; mt<4; mt++)
        ldsm4(a[mt][0],a[mt][1],a[mt][2],a[mt][3], aBase + mt*2304u + kByte);

      uint32_t b0[4], b1[4];
      if (BM==0){
#pragma unroll
        for (int p=0; p<2; p++){
          uint32_t r0,r1,r2,r3;
          ldsm4(r0,r1,r2,r3, bBase0 + p*2304u + kByte);
          b0[2*p]=r0; b1[2*p]=r1; b0[2*p+1]=r2; b1[2*p+1]=r3;
        }
      } else {
#pragma unroll
        for (int p=0; p<2; p++){
          uint32_t r0,r1,r2,r3;
          ldsm4t(r0,r1,r2,r3, bBase1 + p*32u + (stByte + kk*4352u));
          b0[2*p]=r0; b1[2*p]=r1; b0[2*p+1]=r2; b1[2*p+1]=r3;
        }
      }
#pragma unroll
      for (int mt=0; mt<4; mt++)
#pragma unroll
        for (int nt=0; nt<4; nt++)
          mma_h(acc[mt][nt], a[mt][0],a[mt][1],a[mt][2],a[mt][3], b0[nt],b1[nt]);
    }
    cur = (cur==2)?0:cur+1;
  }

#pragma unroll
  for (int mt=0; mt<4; mt++){
#pragma unroll
    for (int nt=0; nt<4; nt++){
#pragma unroll
      for (int i=0; i<4; i++){
        int row = bm0 + wm*64 + mt*16 + g + ((i&2)?8:0);
        int col = bn0 + wn*32 + nt*8 + t*2 + (i&1);
        long long idx = (long long)row*ldc + col;
        float v = acc[mt][nt][i];
        if (bias) v += bias[col];
        if (epi==0)      C[idx] = __float2half_rn(v);
        else if (epi==1) C[idx] = __float2half_rn(gelu_t(v));
        else if (epi==2) C[idx] = __float2half_rn(v*alpha);
        else if (epi==3) C[idx] = __float2half_rn(v + __half2float(C[idx]));
        else             Cf[idx] = v;
      }
    }
  }
}

// ---------------- host orchestration ----------------
struct GArgs {
  const __half *A,*A2,*A3; int lda; long long bsA;
  const __half *B,*B2,*B3; int ldb; long long bsB; int bmode;
  __half *C,*C2,*C3; int ldc; long long bsC;
  float* Cf; long long bsCf;
  int zs1, zs2, M, N, K, batch;
  const float* bias; int bsBias; int epi; float alpha;
};
static void launch_g(const GArgs& a){
  dim3 grid(a.N/128, a.M/128, a.batch);
  size_t shm = STG_B*3;
#define GCALL(BM) gemm_h<BM><<<grid,256,shm>>>( \
      a.A,a.A2,a.A3,a.lda,a.bsA, a.B,a.B2,a.B3,a.ldb,a.bsB, \
      a.C,a.C2,a.C3,a.ldc,a.bsC, a.Cf,a.bsCf, a.zs1,a.zs2, a.K, \
      a.bias,a.bsBias,a.epi,a.alpha)
  if (a.bmode==0) GCALL(0); else GCALL(1);
#undef GCALL
}

extern "C" void kernel_launch(void* const* d_in, const int* in_sizes, int n_in,
                              void* d_out, int out_size){
  const float* hs     = (const float*)d_in[0];
  const float* temb   = (const float*)d_in[1];
  const float* hsc    = (const float*)d_in[2];
  const float* tembc  = (const float*)d_in[3];
  const float* ropec  = (const float*)d_in[4];
  const float* ropes  = (const float*)d_in[5];
  const float* norm_w = (const float*)d_in[6];
  const float* norm_b = (const float*)d_in[7];
  const float* normc_w= (const float*)d_in[8];
  const float* normc_b= (const float*)d_in[9];
  const float* mlp_w  = (const float*)d_in[10];
  const float* mlp_b  = (const float*)d_in[11];
  const float* out_w  = (const float*)d_in[12];
  const float* out_b  = (const float*)d_in[13];
  const float* q_w    = (const float*)d_in[14];
  const float* q_b    = (const float*)d_in[15];
  const float* k_w    = (const float*)d_in[16];
  const float* k_b    = (const float*)d_in[17];
  const float* v_w    = (const float*)d_in[18];
  const float* v_b    = (const float*)d_in[19];
  const float* rms_q  = (const float*)d_in[20];
  const float* rms_k  = (const float*)d_in[21];
  const float* qc_w   = (const float*)d_in[22];
  const float* qc_b   = (const float*)d_in[23];
  const float* kc_w   = (const float*)d_in[24];
  const float* kc_b   = (const float*)d_in[25];
  const float* vc_w   = (const float*)d_in[26];
  const float* vc_b   = (const float*)d_in[27];
  const float* rms_qc = (const float*)d_in[28];
  const float* rms_kc = (const float*)d_in[29];
  float* out = (float*)d_out;

  static __half *p_nh=nullptr, *p_qkv=nullptr, *p_sc=nullptr, *p_hc=nullptr, *p_wh=nullptr;
  static float *p_mod=nullptr, *p_bias=nullptr;
  static cudaStream_t s2;
  static cudaEvent_t evF, evJ;
  if (!p_nh){
    cudaGetSymbolAddress((void**)&p_nh,  g_nh);
    cudaGetSymbolAddress((void**)&p_qkv, g_qkv);
    cudaGetSymbolAddress((void**)&p_sc,  g_sc);
    cudaGetSymbolAddress((void**)&p_hc,  g_hcat);
    cudaGetSymbolAddress((void**)&p_wh,  g_wh);
    cudaGetSymbolAddress((void**)&p_mod, g_mod);
    cudaGetSymbolAddress((void**)&p_bias,g_bias);
    cudaFuncSetAttribute(gemm_h<0>, cudaFuncAttributeMaxDynamicSharedMemorySize, STG_B*3);
    cudaFuncSetAttribute(gemm_h<1>, cudaFuncAttributeMaxDynamicSharedMemorySize, STG_B*3);
    cudaStreamCreateWithFlags(&s2, cudaStreamNonBlocking);
    cudaEventCreateWithFlags(&evF, cudaEventDisableTiming);
    cudaEventCreateWithFlags(&evJ, cudaEventDisableTiming);
  }
  const size_t SD = (size_t)SEQ*DIM;
  __half* nh0 = p_nh;          __half* nh1 = p_nh + SD;
  __half* q   = p_qkv + 0*SD;  __half* kb_ = p_qkv + 1*SD;  __half* v   = p_qkv + 2*SD;
  __half* qc  = p_qkv + 3*SD;  __half* kc  = p_qkv + 4*SD;  __half* vc  = p_qkv + 5*SD;
  __half* hcat0 = p_hc;        __half* hcat1 = p_hc + (size_t)SEQ*CATD;
  float* gate0 = p_mod + 2*DIM;
  const long long SS = (long long)SEQ*SEQ;
  __half* sc_ctrl  = p_sc + 24*SS;
  __half* sc_cross = p_sc + 48*SS;
  float* parts = (float*)p_sc;            // reuse score scratch for out-proj fp32 partials

  __half* wh_q  = p_wh + 0*WC_QKV;
  __half* wh_qc = p_wh + 3*WC_QKV;
  __half* wh_ml = p_wh + 6*WC_QKV;
  __half* wh_ou = p_wh + 6*WC_QKV + WC_MLP;

  // ---- fork: run qkv/out weight cvts + bias pack on side stream, overlapping MLP ----
  cudaEventRecord(evF, 0);
  cudaStreamWaitEvent(s2, evF, 0);
  { int n4 = (int)(WC_QKV/4); dim3 grid((n4+255)/256, 6);
    cvt6_h<<<grid,256,0,s2>>>(q_w,k_w,v_w,qc_w,kc_w,vc_w, p_wh, n4); }
  { int n4 = (int)(WC_OUT/4); cvt_h<<<(n4+255)/256,256,0,s2>>>(out_w, wh_ou, n4); }
  pack_bias_kernel<<<(DIM+255)/256,256,0,s2>>>(q_b,k_b,v_b,qc_b,kc_b,vc_b);
  cudaEventRecord(evJ, s2);

  // ---- main stream ----
  { int n4 = (int)(WC_MLP/4); cvt_h<<<(n4+255)/256,256>>>(mlp_w, wh_ml, n4); }
  { dim3 grid((3*DIM)/8, 2); mod_gemv2<<<grid,256>>>(norm_w,norm_b,temb, normc_w,normc_b,tembc); }
  { dim3 grid(SEQ,2); ln_mod2<<<grid,256>>>(hs, hsc); }
  // MLP both streams, z=2
  { GArgs a{};
    a.A=nh0; a.A2=a.A3=nh0; a.lda=DIM; a.bsA=(long long)SD;
    a.B=wh_ml; a.B2=a.B3=wh_ml; a.ldb=DIM; a.bsB=0; a.bmode=0;
    a.C=hcat0+DIM; a.C2=a.C3=a.C; a.ldc=CATD; a.bsC=(long long)SEQ*CATD;
    a.Cf=nullptr; a.bsCf=0;
    a.zs1=2; a.zs2=2; a.M=SEQ; a.N=MLPD; a.K=DIM; a.batch=2;
    a.bias=mlp_b; a.bsBias=0; a.epi=1; a.alpha=0.f;
    launch_g(a); }
  // join: weight cvts must be done before QKV
  cudaStreamWaitEvent(0, evJ, 0);
  // QKV both streams in ONE z=6 launch (weights/outputs/biases contiguous per group)
  { GArgs a{};
    a.A=nh0; a.A2=nh1; a.A3=nh1; a.lda=DIM; a.bsA=0;
    a.B=wh_q; a.B2=wh_qc; a.B3=wh_qc; a.ldb=DIM; a.bsB=(long long)WC_QKV; a.bmode=0;
    a.C=q; a.C2=qc; a.C3=qc; a.ldc=DIM; a.bsC=(long long)SD;
    a.Cf=nullptr; a.bsCf=0;
    a.zs1=3; a.zs2=6; a.M=SEQ; a.N=DIM; a.K=DIM; a.batch=6;
    a.bias=p_bias; a.bsBias=DIM; a.epi=0; a.alpha=0.f;
    launch_g(a); }
  // RMS + RoPE (q,k,qc,kc)
  { dim3 grid(3072,4); rmsrope_kernel<<<grid,256>>>(p_qkv, rms_q, rms_k, rms_qc, rms_kc, ropec, ropes); }
  // QK^T main+ctrl+cross, z=72
  { GArgs a{};
    a.A=q;  a.A2=qc; a.A3=q;  a.lda=DIM; a.bsA=HD;
    a.B=kb_; a.B2=kc; a.B3=kc; a.ldb=DIM; a.bsB=HD; a.bmode=0;
    a.C=p_sc; a.C2=sc_ctrl; a.C3=sc_cross; a.ldc=SEQ; a.bsC=SS;
    a.Cf=nullptr; a.bsCf=0;
    a.zs1=24; a.zs2=48; a.M=SEQ; a.N=SEQ; a.K=HD; a.batch=72;
    a.bias=nullptr; a.bsBias=0; a.epi=2; a.alpha=INV_SQRT_HD;
    launch_g(a); }
  // softmax 72K rows
  softmax_kernel<<<72*SEQ,256>>>(p_sc);
  // PV main+ctrl, z=48 (BM=1)
  { GArgs a{};
    a.A=p_sc; a.A2=sc_ctrl; a.A3=sc_ctrl; a.lda=SEQ; a.bsA=SS;
    a.B=v; a.B2=vc; a.B3=vc; a.ldb=DIM; a.bsB=HD; a.bmode=1;
    a.C=hcat0; a.C2=hcat1; a.C3=hcat1; a.ldc=CATD; a.bsC=HD;
    a.Cf=nullptr; a.bsCf=0;
    a.zs1=24; a.zs2=48; a.M=SEQ; a.N=HD; a.K=SEQ; a.batch=48;
    a.bias=nullptr; a.bsBias=0; a.epi=0; a.alpha=0.f;
    launch_g(a); }
  // PV cross, accumulate into hcat0 (BM=1)
  { GArgs a{};
    a.A=sc_cross; a.A2=sc_cross; a.A3=sc_cross; a.lda=SEQ; a.bsA=SS;
    a.B=vc; a.B2=vc; a.B3=vc; a.ldb=DIM; a.bsB=HD; a.bmode=1;
    a.C=hcat0; a.C2=hcat0; a.C3=hcat0; a.ldc=CATD; a.bsC=HD;
    a.Cf=nullptr; a.bsCf=0;
    a.zs1=24; a.zs2=24; a.M=SEQ; a.N=HD; a.K=SEQ; a.batch=24;
    a.bias=nullptr; a.bsBias=0; a.epi=3; a.alpha=0.f;
    launch_g(a); }
  // output projection split-K, z=4 -> fp32 partials in score scratch
  { GArgs a{};
    a.A=hcat0; a.A2=hcat0+KHALF; a.A3=hcat1; a.lda=CATD; a.bsA=KHALF;
    a.B=wh_ou; a.B2=wh_ou+KHALF; a.B3=wh_ou; a.ldb=CATD; a.bsB=KHALF; a.bmode=0;
    a.C=nullptr; a.C2=a.C3=nullptr; a.ldc=DIM; a.bsC=0;
    a.Cf=parts; a.bsCf=(long long)SD;
    a.zs1=1; a.zs2=2; a.M=SEQ; a.N=DIM; a.K=KHALF; a.batch=4;
    a.bias=nullptr; a.bsBias=0; a.epi=5; a.alpha=0.f;
    launch_g(a); }
  // combine partials + bias + gate + residual -> out
  { long long n4 = (2*(long long)SD)/4;
    combine_out<<<(unsigned)((n4+255)/256),256>>>(parts, out_b, gate0, hs, hsc, out); }
}

// round 16
// speedup vs baseline: 1.0240x; 1.0130x over previous
#include <cuda_runtime.h>
#include <cuda_fp16.h>
#include <math.h>
#include <stdint.h>

#define SEQ   1024
#define DIM   3072
#define NHDS  24
#define HD    128
#define MLPD  12288
#define CATD  15360
#define KHALF 7680
#define INV_SQRT_HD 0.08838834764831845f

#define WC_QKV   ((size_t)DIM*DIM)
#define WC_MLP   ((size_t)MLPD*DIM)
#define WC_OUT   ((size_t)DIM*CATD)

// ---------------- scratch (device globals; no allocation allowed) ----------------
__device__ float  g_mod[2][3*DIM];
__device__ float  g_bias[2][3*DIM];
__device__ __half g_nh[2][SEQ*DIM];             // ln output; reused as PV-cross scratch later
__device__ __half g_qkv[6][SEQ*DIM];            // q,k,v,qc,kc,vc
__device__ __half g_sc[(size_t)72*SEQ*SEQ];     // scores; later reused as fp32 out-proj partials
__device__ __half g_hcat[2][SEQ*CATD];
__device__ __half g_wh[6*WC_QKV + WC_MLP + WC_OUT];

// ---------------- helpers ----------------
__device__ __forceinline__ float gelu_t(float x){
  float u = 0.7978845608028654f*(x + 0.044715f*x*x*x);
  return 0.5f*x*(1.f + tanhf(u));
}
__device__ __forceinline__ void cpa16(const void* s, const void* g){
  unsigned sa = (unsigned)__cvta_generic_to_shared(s);
  asm volatile("cp.async.cg.shared.global [%0], [%1], 16;" :: "r"(sa), "l"(g));
}
__device__ __forceinline__ void cpcommit(){ asm volatile("cp.async.commit_group;"); }
template<int N> __device__ __forceinline__ void cpwait(){ asm volatile("cp.async.wait_group %0;"::"n"(N)); }
__device__ __forceinline__ void ldsm4(uint32_t& r0,uint32_t& r1,uint32_t& r2,uint32_t& r3,uint32_t addr){
  asm volatile("ldmatrix.sync.aligned.m8n8.x4.shared.b16 {%0,%1,%2,%3}, [%4];"
               : "=r"(r0),"=r"(r1),"=r"(r2),"=r"(r3) : "r"(addr));
}
__device__ __forceinline__ void ldsm4t(uint32_t& r0,uint32_t& r1,uint32_t& r2,uint32_t& r3,uint32_t addr){
  asm volatile("ldmatrix.sync.aligned.m8n8.x4.trans.shared.b16 {%0,%1,%2,%3}, [%4];"
               : "=r"(r0),"=r"(r1),"=r"(r2),"=r"(r3) : "r"(addr));
}
__device__ __forceinline__ void mma_h(float d[4], uint32_t A0,uint32_t A1,uint32_t A2,uint32_t A3,
                                      uint32_t B0,uint32_t B1){
  asm volatile("mma.sync.aligned.m16n8k16.row.col.f32.f16.f16.f32 "
               "{%0,%1,%2,%3},{%4,%5,%6,%7},{%8,%9},{%0,%1,%2,%3};"
               : "+f"(d[0]),"+f"(d[1]),"+f"(d[2]),"+f"(d[3])
               : "r"(A0),"r"(A1),"r"(A2),"r"(A3),"r"(B0),"r"(B1));
}

// ---------------- f32 -> f16 weight conversion ----------------
__global__ void cvt_h(const float* __restrict__ src, __half* __restrict__ dst, int n4){
  int i = blockIdx.x*blockDim.x + threadIdx.x;
  if (i < n4){
    float4 v = ((const float4*)src)[i];
    ((__half2*)dst)[2*i]   = __floats2half2_rn(v.x, v.y);
    ((__half2*)dst)[2*i+1] = __floats2half2_rn(v.z, v.w);
  }
}
__global__ void cvt6_h(const float* s0,const float* s1,const float* s2,
                       const float* s3,const float* s4,const float* s5,
                       __half* __restrict__ dst, int n4){
  const float* srcs[6] = {s0,s1,s2,s3,s4,s5};
  const float* src = srcs[blockIdx.y];
  __half* d = dst + (size_t)blockIdx.y*(size_t)n4*4;
  int i = blockIdx.x*blockDim.x + threadIdx.x;
  if (i < n4){
    float4 v = ((const float4*)src)[i];
    ((__half2*)d)[2*i]   = __floats2half2_rn(v.x, v.y);
    ((__half2*)d)[2*i+1] = __floats2half2_rn(v.z, v.w);
  }
}

// ---------------- pack q/k/v biases ----------------
__global__ void pack_bias_kernel(const float* __restrict__ qb, const float* __restrict__ kb,
                                 const float* __restrict__ vb, const float* __restrict__ qcb,
                                 const float* __restrict__ kcb, const float* __restrict__ vcb){
  int i = blockIdx.x*blockDim.x + threadIdx.x;
  if (i < DIM){
    g_bias[0][i] = qb[i];  g_bias[0][DIM+i] = kb[i];  g_bias[0][2*DIM+i] = vb[i];
    g_bias[1][i] = qcb[i]; g_bias[1][DIM+i] = kcb[i]; g_bias[1][2*DIM+i] = vcb[i];
  }
}

// ---------------- fused silu + modulation GEMV ----------------
__global__ void mod_gemv2(const float* __restrict__ w0, const float* __restrict__ b0,
                          const float* __restrict__ t0,
                          const float* __restrict__ w1, const float* __restrict__ b1,
                          const float* __restrict__ t1){
  __shared__ float ssil[DIM];
  const int stream = blockIdx.y;
  const float* w = stream ? w1 : w0;
  const float* b = stream ? b1 : b0;
  const float* t = stream ? t1 : t0;
  for (int i=threadIdx.x; i<DIM; i+=256){
    float x = t[i]; ssil[i] = x/(1.f+expf(-x));
  }
  __syncthreads();
  int warp = (blockIdx.x*blockDim.x + threadIdx.x) >> 5;
  int lane = threadIdx.x & 31;
  if (warp >= 3*DIM) return;
  const float4* wv = (const float4*)(w + (size_t)warp*DIM);
  const float4* sv = (const float4*)ssil;
  float acc = 0.f;
  for (int i = lane; i < DIM/4; i += 32){
    float4 a = wv[i], c = sv[i];
    acc += a.x*c.x + a.y*c.y + a.z*c.z + a.w*c.w;
  }
#pragma unroll
  for (int o=16;o;o>>=1) acc += __shfl_xor_sync(0xffffffffu, acc, o);
  if (!lane) g_mod[stream][warp] = acc + b[warp];
}

// ---------------- LayerNorm + modulate (half out) ----------------
__global__ void ln_mod2(const float* __restrict__ x0, const float* __restrict__ x1){
  __shared__ float sh[66];
  const int stream = blockIdx.y;
  const float* x = stream ? x1 : x0;
  int s = blockIdx.x;
  const float* row = x + (size_t)s*DIM;
  float sum=0.f, sq=0.f;
  for (int i=threadIdx.x; i<DIM; i+=256){ float v=row[i]; sum+=v; sq+=v*v; }
#pragma unroll
  for (int o=16;o;o>>=1){
    sum += __shfl_xor_sync(0xffffffffu,sum,o);
    sq  += __shfl_xor_sync(0xffffffffu,sq,o);
  }
  int w=threadIdx.x>>5, l=threadIdx.x&31;
  if (!l){ sh[w]=sum; sh[32+w]=sq; }
  __syncthreads();
  if (threadIdx.x==0){
    float a=0.f,b=0.f;
#pragma unroll
    for (int i=0;i<8;i++){ a+=sh[i]; b+=sh[32+i]; }
    sh[64]=a; sh[65]=b;
  }
  __syncthreads();
  float mu = sh[64]*(1.f/DIM);
  float var = sh[65]*(1.f/DIM) - mu*mu;
  float rstd = rsqrtf(var + 1e-6f);
  const float* shift = g_mod[stream];
  const float* scale = g_mod[stream] + DIM;
  __half* out = g_nh[stream] + (size_t)s*DIM;
  for (int i=threadIdx.x; i<DIM; i+=256)
    out[i] = __float2half_rn((row[i]-mu)*rstd*(1.f+scale[i]) + shift[i]);
}

// ---------------- per-(s,head) RMS + RoPE on half buffers ----------------
__global__ void rmsrope_kernel(__half* __restrict__ qkvbase,
                               const float* __restrict__ w0, const float* __restrict__ w1,
                               const float* __restrict__ w2, const float* __restrict__ w3,
                               const float* __restrict__ cosb, const float* __restrict__ sinb){
  const int bufsel[4] = {0,1,3,4};
  int b = blockIdx.y;
  __half* buf = qkvbase + (size_t)bufsel[b]*SEQ*DIM;
  const float* w = (b==0)?w0:(b==1)?w1:(b==2)?w2:w3;
  int idx  = blockIdx.x*blockDim.x + threadIdx.x;
  int warp = idx >> 5, lane = idx & 31;
  int s = warp / NHDS, h = warp % NHDS;
  uint2* row = (uint2*)(buf + (size_t)s*DIM + h*HD);
  uint2 raw = row[lane];
  __half2 p01 = *reinterpret_cast<__half2*>(&raw.x);
  __half2 p23 = *reinterpret_cast<__half2*>(&raw.y);
  float v0=__low2float(p01), v1=__high2float(p01);
  float v2=__low2float(p23), v3=__high2float(p23);
  float sq = v0*v0+v1*v1+v2*v2+v3*v3;
#pragma unroll
  for (int o=16;o;o>>=1) sq += __shfl_xor_sync(0xffffffffu, sq, o);
  float rstd = rsqrtf(sq*(1.f/HD) + 1e-6f);
  int d = lane*4;
  float4 wv = *(const float4*)(w + d);
  float4 cv = *(const float4*)(cosb + s*HD + d);
  float4 sv = *(const float4*)(sinb + s*HD + d);
  float x0=v0*rstd*wv.x, x1=v1*rstd*wv.y, x2=v2*rstd*wv.z, x3=v3*rstd*wv.w;
  float o0 = x0*cv.x - x1*sv.x;
  float o1 = x1*cv.y + x0*sv.y;
  float o2 = x2*cv.z - x3*sv.z;
  float o3 = x3*cv.w + x2*sv.w;
  __half2 q01 = __floats2half2_rn(o0,o1);
  __half2 q23 = __floats2half2_rn(o2,o3);
  raw.x = *reinterpret_cast<uint32_t*>(&q01);
  raw.y = *reinterpret_cast<uint32_t*>(&q23);
  row[lane] = raw;
}

// ---------------- row softmax, smem-cached (1 global read + 1 global write) ----------------
__global__ void softmax_kernel(__half* __restrict__ p){
  __shared__ __half2 srow[SEQ/2];
  __shared__ float sh[36];
  __half2* row = (__half2*)(p + (size_t)blockIdx.x*SEQ);
  int tid=threadIdx.x, w=tid>>5, l=tid&31;
  float m = -1e30f;
#pragma unroll
  for (int i=tid;i<SEQ/2;i+=256){
    __half2 v = row[i];
    srow[i] = v;
    m = fmaxf(m, fmaxf(__low2float(v), __high2float(v)));
  }
#pragma unroll
  for (int o=16;o;o>>=1) m = fmaxf(m, __shfl_xor_sync(0xffffffffu,m,o));
  if (!l) sh[w]=m;
  __syncthreads();
  if (tid==0){ float mm=sh[0]; for(int i=1;i<8;i++) mm=fmaxf(mm,sh[i]); sh[32]=mm; }
  __syncthreads();
  m = sh[32];
  float sum=0.f;
#pragma unroll
  for (int i=tid;i<SEQ/2;i+=256){
    __half2 v = srow[i];
    float e0 = expf(__low2float(v)-m);
    float e1 = expf(__high2float(v)-m);
    srow[i] = __floats2half2_rn(e0,e1);
    sum += e0+e1;
  }
#pragma unroll
  for (int o=16;o;o>>=1) sum += __shfl_xor_sync(0xffffffffu,sum,o);
  if (!l) sh[8+w]=sum;
  __syncthreads();
  if (tid==0){ float ss=0.f; for(int i=0;i<8;i++) ss+=sh[8+i]; sh[33]=ss; }
  __syncthreads();
  float inv = 1.f/sh[33];
#pragma unroll
  for (int i=tid;i<SEQ/2;i+=256){
    __half2 v = srow[i];
    row[i] = __floats2half2_rn(__low2float(v)*inv, __high2float(v)*inv);
  }
}

// ---------------- add PV-cross scratch into hcat0 attn columns ----------------
__global__ void add_cross(const __half* __restrict__ cross, __half* __restrict__ hcat){
  int idx = blockIdx.x*blockDim.x + threadIdx.x;      // over SEQ*DIM/2 half2
  if (idx >= SEQ*DIM/2) return;
  int rw = idx / (DIM/2), cl = idx % (DIM/2);
  __half2 a = ((const __half2*)cross)[idx];
  __half2* dst = (__half2*)hcat + (size_t)rw*(CATD/2) + cl;
  __half2 b = *dst;
  *dst = __floats2half2_rn(__low2float(a)+__low2float(b), __high2float(a)+__high2float(b));
}

// ---------------- combine out-proj partials: out = res + gate*(p_lo+p_hi+bias) ----------------
__global__ void combine_out(const float* __restrict__ parts, const float* __restrict__ outb,
                            const float* __restrict__ gates, const float* __restrict__ hs,
                            const float* __restrict__ hsc, float* __restrict__ out){
  const long long SD = (long long)SEQ*DIM;
  long long i4 = (long long)blockIdx.x*blockDim.x + threadIdx.x;
  if (i4 >= (2*SD)/4) return;
  long long i = i4*4;
  int stream = (i >= SD);
  long long li = i - (long long)stream*SD;
  int col = (int)(li % DIM);
  const float4 p1 = *(const float4*)(parts + (2*stream+0)*SD + li);
  const float4 p2 = *(const float4*)(parts + (2*stream+1)*SD + li);
  const float4 bb = *(const float4*)(outb + col);
  const float4 gg = *(const float4*)(gates + (size_t)stream*3*DIM + col);
  const float4 rr = *(const float4*)((stream ? hsc : hs) + li);
  float4 o;
  o.x = rr.x + gg.x*(p1.x+p2.x+bb.x);
  o.y = rr.y + gg.y*(p1.y+p2.y+bb.y);
  o.z = rr.z + gg.z*(p1.z+p2.z+bb.z);
  o.w = rr.w + gg.w*(p1.w+p2.w+bb.w);
  *(float4*)(out + i) = o;
}

// ================ 3-stage pipelined FP16 GEMM (m16n8k16, fp32 acc) ================
// BM=0: B [N,K] row-major (LDSM).  BM=1: B [K,N] row-major (LDSM.trans; PV).
// Per-z-group ldc (ldc1/ldc2/ldc3).
// epi: 0=bias->half, 1=gelu(bias)->half, 2=*alpha->half, 3=acc+=Chalf->half, 5=raw float partial
#define AST   72
#define BST1  136
#define STG_H 18432
#define STG_B 36864
template<int BM>
__global__ __launch_bounds__(256,2) void gemm_h(
    const __half* __restrict__ A,  const __half* __restrict__ A2, const __half* __restrict__ A3,
    int lda, long long bsA,
    const __half* __restrict__ B,  const __half* __restrict__ B2, const __half* __restrict__ B3,
    int ldb, long long bsB,
    __half* __restrict__ C,  __half* __restrict__ C2, __half* __restrict__ C3,
    int ldc1, int ldc2, int ldc3, long long bsC,
    float* __restrict__ Cf, long long bsCf,
    int zs1, int zs2,
    int K,
    const float* __restrict__ bias, int bsBias, int epi, float alpha)
{
  extern __shared__ __half smh[];
  const int z = blockIdx.z;
  int ldc = ldc1;
  {
    long long zo;
    if (z < zs1){ zo = z; }
    else if (z < zs2){ A = A2; B = B2; C = C2; ldc = ldc2; zo = z - zs1; }
    else { A = A3; B = B3; C = C3; ldc = ldc3; zo = z - zs2; }
    A += zo*bsA;  B += zo*bsB;  C += zo*bsC;
  }
  if (Cf) Cf += (long long)z*bsCf;
  if (bias) bias += (long long)z*bsBias;
  const int bm0 = blockIdx.y*128, bn0 = blockIdx.x*128;
  const int tid = threadIdx.x;
  const int warp = tid>>5, lane = tid&31;
  const int wm = warp&1, wn = warp>>1;
  const int g = lane>>2, t = lane&3;
  const int j = lane>>3;

  const uint32_t smemBase = (uint32_t)__cvta_generic_to_shared(smh);
  const uint32_t aBase  = smemBase + (uint32_t)(((wm*64 + (j&1)*8 + (lane&7))*AST + (j>>1)*8)<<1);
  const uint32_t bBase0 = smemBase + (uint32_t)((9216 + (wn*32 + (j>>1)*8 + (lane&7))*AST + (j&1)*8)<<1);
  const uint32_t bBase1 = smemBase + (uint32_t)((9216 + ((j&1)*8 + (lane&7))*BST1 + wn*32 + (j>>1)*8)<<1);

  auto load_tile = [&](int kt, int buf){
    __half* As = smh + buf*STG_H;
    __half* Bs = As + 9216;
    const int k0 = kt<<6;
    {
      const int c8=(tid&7)*8, r=tid>>3;
#pragma unroll
      for (int it=0; it<4; it++){
        int row=r+it*32;
        cpa16(As + row*AST + c8, A + (long long)(bm0+row)*lda + (k0+c8));
      }
    }
    if (BM==0){
      const int c8=(tid&7)*8, r=tid>>3;
#pragma unroll
      for (int it=0; it<4; it++){
        int row=r+it*32;
        cpa16(Bs + row*AST + c8, B + (long long)(bn0+row)*ldb + (k0+c8));
      }
    } else {
      const int n8=(tid&15)*8, r=tid>>4;
#pragma unroll
      for (int it=0; it<4; it++){
        int kk=r+it*16;
        cpa16(Bs + kk*BST1 + n8, B + (long long)(k0+kk)*ldb + (bn0+n8));
      }
    }
  };

  float acc[4][4][4];
#pragma unroll
  for (int a=0;a<4;a++)
#pragma unroll
    for (int b=0;b<4;b++)
#pragma unroll
      for (int c=0;c<4;c++) acc[a][b][c]=0.f;

  const int KT = K >> 6;
  load_tile(0,0); cpcommit();
  if (KT > 1){ load_tile(1,1); cpcommit(); }
  int cur = 0, nxt = 2;

  for (int kt=0; kt<KT; kt++){
    if (kt+1 < KT) cpwait<1>(); else cpwait<0>();
    __syncthreads();
    if (kt+2 < KT){
      load_tile(kt+2, nxt); cpcommit();
      nxt = (nxt==2)?0:nxt+1;
    }
    const uint32_t stByte = cur*STG_B;

#pragma unroll
    for (int kk=0; kk<4; kk++){
      const uint32_t kByte = stByte + kk*32;
      uint32_t a[4][4];
#pragma unroll
      for (int mt=0; mt<4; mt++)
        ldsm4(a[mt][0],a[mt][1],a[mt][2],a[mt][3], aBase + mt*2304u + kByte);

      uint32_t b0[4], b1[4];
      if (BM==0){
#pragma unroll
        for (int p=0; p<2; p++){
          uint32_t r0,r1,r2,r3;
          ldsm4(r0,r1,r2,r3, bBase0 + p*2304u + kByte);
          b0[2*p]=r0; b1[2*p]=r1; b0[2*p+1]=r2; b1[2*p+1]=r3;
        }
      } else {
#pragma unroll
        for (int p=0; p<2; p++){
          uint32_t r0,r1,r2,r3;
          ldsm4t(r0,r1,r2,r3, bBase1 + p*32u + (stByte + kk*4352u));
          b0[2*p]=r0; b1[2*p]=r1; b0[2*p+1]=r2; b1[2*p+1]=r3;
        }
      }
#pragma unroll
      for (int mt=0; mt<4; mt++)
#pragma unroll
        for (int nt=0; nt<4; nt++)
          mma_h(acc[mt][nt], a[mt][0],a[mt][1],a[mt][2],a[mt][3], b0[nt],b1[nt]);
    }
    cur = (cur==2)?0:cur+1;
  }

#pragma unroll
  for (int mt=0; mt<4; mt++){
#pragma unroll
    for (int nt=0; nt<4; nt++){
#pragma unroll
      for (int i=0; i<4; i++){
        int row = bm0 + wm*64 + mt*16 + g + ((i&2)?8:0);
        int col = bn0 + wn*32 + nt*8 + t*2 + (i&1);
        long long idx = (long long)row*ldc + col;
        float v = acc[mt][nt][i];
        if (bias) v += bias[col];
        if (epi==0)      C[idx] = __float2half_rn(v);
        else if (epi==1) C[idx] = __float2half_rn(gelu_t(v));
        else if (epi==2) C[idx] = __float2half_rn(v*alpha);
        else if (epi==3) C[idx] = __float2half_rn(v + __half2float(C[idx]));
        else             Cf[idx] = v;
      }
    }
  }
}

// ---------------- host orchestration ----------------
struct GArgs {
  const __half *A,*A2,*A3; int lda; long long bsA;
  const __half *B,*B2,*B3; int ldb; long long bsB; int bmode;
  __half *C,*C2,*C3; int ldc, ldc2, ldc3; long long bsC;
  float* Cf; long long bsCf;
  int zs1, zs2, M, N, K, batch;
  const float* bias; int bsBias; int epi; float alpha;
};
static void launch_g(const GArgs& a){
  dim3 grid(a.N/128, a.M/128, a.batch);
  size_t shm = STG_B*3;
#define GCALL(BM) gemm_h<BM><<<grid,256,shm>>>( \
      a.A,a.A2,a.A3,a.lda,a.bsA, a.B,a.B2,a.B3,a.ldb,a.bsB, \
      a.C,a.C2,a.C3,a.ldc,a.ldc2,a.ldc3,a.bsC, a.Cf,a.bsCf, a.zs1,a.zs2, a.K, \
      a.bias,a.bsBias,a.epi,a.alpha)
  if (a.bmode==0) GCALL(0); else GCALL(1);
#undef GCALL
}

extern "C" void kernel_launch(void* const* d_in, const int* in_sizes, int n_in,
                              void* d_out, int out_size){
  const float* hs     = (const float*)d_in[0];
  const float* temb   = (const float*)d_in[1];
  const float* hsc    = (const float*)d_in[2];
  const float* tembc  = (const float*)d_in[3];
  const float* ropec  = (const float*)d_in[4];
  const float* ropes  = (const float*)d_in[5];
  const float* norm_w = (const float*)d_in[6];
  const float* norm_b = (const float*)d_in[7];
  const float* normc_w= (const float*)d_in[8];
  const float* normc_b= (const float*)d_in[9];
  const float* mlp_w  = (const float*)d_in[10];
  const float* mlp_b  = (const float*)d_in[11];
  const float* out_w  = (const float*)d_in[12];
  const float* out_b  = (const float*)d_in[13];
  const float* q_w    = (const float*)d_in[14];
  const float* q_b    = (const float*)d_in[15];
  const float* k_w    = (const float*)d_in[16];
  const float* k_b    = (const float*)d_in[17];
  const float* v_w    = (const float*)d_in[18];
  const float* v_b    = (const float*)d_in[19];
  const float* rms_q  = (const float*)d_in[20];
  const float* rms_k  = (const float*)d_in[21];
  const float* qc_w   = (const float*)d_in[22];
  const float* qc_b   = (const float*)d_in[23];
  const float* kc_w   = (const float*)d_in[24];
  const float* kc_b   = (const float*)d_in[25];
  const float* vc_w   = (const float*)d_in[26];
  const float* vc_b   = (const float*)d_in[27];
  const float* rms_qc = (const float*)d_in[28];
  const float* rms_kc = (const float*)d_in[29];
  float* out = (float*)d_out;

  static __half *p_nh=nullptr, *p_qkv=nullptr, *p_sc=nullptr, *p_hc=nullptr, *p_wh=nullptr;
  static float *p_mod=nullptr, *p_bias=nullptr;
  static cudaStream_t s2;
  static cudaEvent_t evF, evJ;
  if (!p_nh){
    cudaGetSymbolAddress((void**)&p_nh,  g_nh);
    cudaGetSymbolAddress((void**)&p_qkv, g_qkv);
    cudaGetSymbolAddress((void**)&p_sc,  g_sc);
    cudaGetSymbolAddress((void**)&p_hc,  g_hcat);
    cudaGetSymbolAddress((void**)&p_wh,  g_wh);
    cudaGetSymbolAddress((void**)&p_mod, g_mod);
    cudaGetSymbolAddress((void**)&p_bias,g_bias);
    cudaFuncSetAttribute(gemm_h<0>, cudaFuncAttributeMaxDynamicSharedMemorySize, STG_B*3);
    cudaFuncSetAttribute(gemm_h<1>, cudaFuncAttributeMaxDynamicSharedMemorySize, STG_B*3);
    cudaStreamCreateWithFlags(&s2, cudaStreamNonBlocking);
    cudaEventCreateWithFlags(&evF, cudaEventDisableTiming);
    cudaEventCreateWithFlags(&evJ, cudaEventDisableTiming);
  }
  const size_t SD = (size_t)SEQ*DIM;
  __half* nh0 = p_nh;          __half* nh1 = p_nh + SD;
  __half* q   = p_qkv + 0*SD;  __half* kb_ = p_qkv + 1*SD;  __half* v   = p_qkv + 2*SD;
  __half* qc  = p_qkv + 3*SD;  __half* kc  = p_qkv + 4*SD;  __half* vc  = p_qkv + 5*SD;
  __half* hcat0 = p_hc;        __half* hcat1 = p_hc + (size_t)SEQ*CATD;
  float* gate0 = p_mod + 2*DIM;
  const long long SS = (long long)SEQ*SEQ;
  __half* sc_ctrl  = p_sc + 24*SS;
  __half* sc_cross = p_sc + 48*SS;
  float* parts = (float*)p_sc;            // out-proj fp32 partials (reuses main-score region)
  __half* pv_cross = nh0;                 // nh is dead after QKV; reuse for PV-cross output

  __half* wh_q  = p_wh + 0*WC_QKV;
  __half* wh_qc = p_wh + 3*WC_QKV;
  __half* wh_ml = p_wh + 6*WC_QKV;
  __half* wh_ou = p_wh + 6*WC_QKV + WC_MLP;

  // ---- fork: qkv/out weight cvts + bias pack on side stream ----
  cudaEventRecord(evF, 0);
  cudaStreamWaitEvent(s2, evF, 0);
  { int n4 = (int)(WC_QKV/4); dim3 grid((n4+255)/256, 6);
    cvt6_h<<<grid,256,0,s2>>>(q_w,k_w,v_w,qc_w,kc_w,vc_w, p_wh, n4); }
  { int n4 = (int)(WC_OUT/4); cvt_h<<<(n4+255)/256,256,0,s2>>>(out_w, wh_ou, n4); }
  pack_bias_kernel<<<(DIM+255)/256,256,0,s2>>>(q_b,k_b,v_b,qc_b,kc_b,vc_b);
  cudaEventRecord(evJ, s2);

  // ---- main stream ----
  { int n4 = (int)(WC_MLP/4); cvt_h<<<(n4+255)/256,256>>>(mlp_w, wh_ml, n4); }
  { dim3 grid((3*DIM)/8, 2); mod_gemv2<<<grid,256>>>(norm_w,norm_b,temb, normc_w,normc_b,tembc); }
  { dim3 grid(SEQ,2); ln_mod2<<<grid,256>>>(hs, hsc); }
  // MLP both streams, z=2
  { GArgs a{};
    a.A=nh0; a.A2=a.A3=nh0; a.lda=DIM; a.bsA=(long long)SD;
    a.B=wh_ml; a.B2=a.B3=wh_ml; a.ldb=DIM; a.bsB=0; a.bmode=0;
    a.C=hcat0+DIM; a.C2=a.C3=a.C; a.ldc=a.ldc2=a.ldc3=CATD; a.bsC=(long long)SEQ*CATD;
    a.Cf=nullptr; a.bsCf=0;
    a.zs1=2; a.zs2=2; a.M=SEQ; a.N=MLPD; a.K=DIM; a.batch=2;
    a.bias=mlp_b; a.bsBias=0; a.epi=1; a.alpha=0.f;
    launch_g(a); }
  cudaStreamWaitEvent(0, evJ, 0);
  // QKV both streams in ONE z=6 launch
  { GArgs a{};
    a.A=nh0; a.A2=nh1; a.A3=nh1; a.lda=DIM; a.bsA=0;
    a.B=wh_q; a.B2=wh_qc; a.B3=wh_qc; a.ldb=DIM; a.bsB=(long long)WC_QKV; a.bmode=0;
    a.C=q; a.C2=qc; a.C3=qc; a.ldc=a.ldc2=a.ldc3=DIM; a.bsC=(long long)SD;
    a.Cf=nullptr; a.bsCf=0;
    a.zs1=3; a.zs2=6; a.M=SEQ; a.N=DIM; a.K=DIM; a.batch=6;
    a.bias=p_bias; a.bsBias=DIM; a.epi=0; a.alpha=0.f;
    launch_g(a); }
  // RMS + RoPE (q,k,qc,kc)
  { dim3 grid(3072,4); rmsrope_kernel<<<grid,256>>>(p_qkv, rms_q, rms_k, rms_qc, rms_kc, ropec, ropes); }
  // QK^T main+ctrl+cross, z=72
  { GArgs a{};
    a.A=q;  a.A2=qc; a.A3=q;  a.lda=DIM; a.bsA=HD;
    a.B=kb_; a.B2=kc; a.B3=kc; a.ldb=DIM; a.bsB=HD; a.bmode=0;
    a.C=p_sc; a.C2=sc_ctrl; a.C3=sc_cross; a.ldc=a.ldc2=a.ldc3=SEQ; a.bsC=SS;
    a.Cf=nullptr; a.bsCf=0;
    a.zs1=24; a.zs2=48; a.M=SEQ; a.N=SEQ; a.K=HD; a.batch=72;
    a.bias=nullptr; a.bsBias=0; a.epi=2; a.alpha=INV_SQRT_HD;
    launch_g(a); }
  // softmax 72K rows (smem-cached)
  softmax_kernel<<<72*SEQ,256>>>(p_sc);
  // PV main+ctrl+cross in ONE z=72 launch; cross -> pv_cross scratch (ldc=DIM)
  { GArgs a{};
    a.A=p_sc; a.A2=sc_ctrl; a.A3=sc_cross; a.lda=SEQ; a.bsA=SS;
    a.B=v; a.B2=vc; a.B3=vc; a.ldb=DIM; a.bsB=HD; a.bmode=1;
    a.C=hcat0; a.C2=hcat1; a.C3=pv_cross; a.ldc=CATD; a.ldc2=CATD; a.ldc3=DIM; a.bsC=HD;
    a.Cf=nullptr; a.bsCf=0;
    a.zs1=24; a.zs2=48; a.M=SEQ; a.N=HD; a.K=SEQ; a.batch=72;
    a.bias=nullptr; a.bsBias=0; a.epi=0; a.alpha=0.f;
    launch_g(a); }
  // fold cross into hcat0 attn columns
  add_cross<<<(SEQ*DIM/2+255)/256,256>>>(pv_cross, hcat0);
  // output projection split-K, z=4 -> fp32 partials
  { GArgs a{};
    a.A=hcat0; a.A2=hcat0+KHALF; a.A3=hcat1; a.lda=CATD; a.bsA=KHALF;
    a.B=wh_ou; a.B2=wh_ou+KHALF; a.B3=wh_ou; a.ldb=CATD; a.bsB=KHALF; a.bmode=0;
    a.C=nullptr; a.C2=a.C3=nullptr; a.ldc=a.ldc2=a.ldc3=DIM; a.bsC=0;
    a.Cf=parts; a.bsCf=(long long)SD;
    a.zs1=1; a.zs2=2; a.M=SEQ; a.N=DIM; a.K=KHALF; a.batch=4;
    a.bias=nullptr; a.bsBias=0; a.epi=5; a.alpha=0.f;
    launch_g(a); }
  // combine partials + bias + gate + residual -> out
  { long long n4 = (2*(long long)SD)/4;
    combine_out<<<(unsigned)((n4+255)/256),256>>>(parts, out_b, gate0, hs, hsc, out); }
}

// round 17
// speedup vs baseline: 1.0659x; 1.0410x over previous
#include <cuda_runtime.h>
#include <cuda_fp16.h>
#include <math.h>
#include <stdint.h>

#define SEQ   1024
#define DIM   3072
#define NHDS  24
#define HD    128
#define MLPD  12288
#define CATD  15360
#define KHALF 7680
#define INV_SQRT_HD 0.08838834764831845f

#define WC_QKV   ((size_t)DIM*DIM)
#define WC_MLP   ((size_t)MLPD*DIM)
#define WC_OUT   ((size_t)DIM*CATD)

// ---------------- scratch (device globals; no allocation allowed) ----------------
__device__ float  g_mod[2][3*DIM];
__device__ float  g_bias[2][3*DIM];
__device__ __half g_nh[2][SEQ*DIM];             // ln output (alive until MLP completes)
__device__ __half g_qkv[6][SEQ*DIM];            // q,k,v,qc,kc,vc
__device__ __half g_pvx[SEQ*DIM];               // PV-cross scratch
__device__ __half g_sc[(size_t)72*SEQ*SEQ];     // scores; later reused as fp32 out-proj partials
__device__ __half g_hcat[2][SEQ*CATD];
__device__ __half g_wh[6*WC_QKV + WC_MLP + WC_OUT];

// ---------------- helpers ----------------
__device__ __forceinline__ float gelu_t(float x){
  float u = 0.7978845608028654f*(x + 0.044715f*x*x*x);
  return 0.5f*x*(1.f + tanhf(u));
}
__device__ __forceinline__ void cpa16(const void* s, const void* g){
  unsigned sa = (unsigned)__cvta_generic_to_shared(s);
  asm volatile("cp.async.cg.shared.global [%0], [%1], 16;" :: "r"(sa), "l"(g));
}
__device__ __forceinline__ void cpcommit(){ asm volatile("cp.async.commit_group;"); }
template<int N> __device__ __forceinline__ void cpwait(){ asm volatile("cp.async.wait_group %0;"::"n"(N)); }
__device__ __forceinline__ void ldsm4(uint32_t& r0,uint32_t& r1,uint32_t& r2,uint32_t& r3,uint32_t addr){
  asm volatile("ldmatrix.sync.aligned.m8n8.x4.shared.b16 {%0,%1,%2,%3}, [%4];"
               : "=r"(r0),"=r"(r1),"=r"(r2),"=r"(r3) : "r"(addr));
}
__device__ __forceinline__ void ldsm4t(uint32_t& r0,uint32_t& r1,uint32_t& r2,uint32_t& r3,uint32_t addr){
  asm volatile("ldmatrix.sync.aligned.m8n8.x4.trans.shared.b16 {%0,%1,%2,%3}, [%4];"
               : "=r"(r0),"=r"(r1),"=r"(r2),"=r"(r3) : "r"(addr));
}
__device__ __forceinline__ void mma_h(float d[4], uint32_t A0,uint32_t A1,uint32_t A2,uint32_t A3,
                                      uint32_t B0,uint32_t B1){
  asm volatile("mma.sync.aligned.m16n8k16.row.col.f32.f16.f16.f32 "
               "{%0,%1,%2,%3},{%4,%5,%6,%7},{%8,%9},{%0,%1,%2,%3};"
               : "+f"(d[0]),"+f"(d[1]),"+f"(d[2]),"+f"(d[3])
               : "r"(A0),"r"(A1),"r"(A2),"r"(A3),"r"(B0),"r"(B1));
}

// ---------------- f32 -> f16 weight conversion ----------------
__global__ void cvt_h(const float* __restrict__ src, __half* __restrict__ dst, int n4){
  int i = blockIdx.x*blockDim.x + threadIdx.x;
  if (i < n4){
    float4 v = ((const float4*)src)[i];
    ((__half2*)dst)[2*i]   = __floats2half2_rn(v.x, v.y);
    ((__half2*)dst)[2*i+1] = __floats2half2_rn(v.z, v.w);
  }
}
__global__ void cvt6_h(const float* s0,const float* s1,const float* s2,
                       const float* s3,const float* s4,const float* s5,
                       __half* __restrict__ dst, int n4){
  const float* srcs[6] = {s0,s1,s2,s3,s4,s5};
  const float* src = srcs[blockIdx.y];
  __half* d = dst + (size_t)blockIdx.y*(size_t)n4*4;
  int i = blockIdx.x*blockDim.x + threadIdx.x;
  if (i < n4){
    float4 v = ((const float4*)src)[i];
    ((__half2*)d)[2*i]   = __floats2half2_rn(v.x, v.y);
    ((__half2*)d)[2*i+1] = __floats2half2_rn(v.z, v.w);
  }
}

// ---------------- pack q/k/v biases ----------------
__global__ void pack_bias_kernel(const float* __restrict__ qb, const float* __restrict__ kb,
                                 const float* __restrict__ vb, const float* __restrict__ qcb,
                                 const float* __restrict__ kcb, const float* __restrict__ vcb){
  int i = blockIdx.x*blockDim.x + threadIdx.x;
  if (i < DIM){
    g_bias[0][i] = qb[i];  g_bias[0][DIM+i] = kb[i];  g_bias[0][2*DIM+i] = vb[i];
    g_bias[1][i] = qcb[i]; g_bias[1][DIM+i] = kcb[i]; g_bias[1][2*DIM+i] = vcb[i];
  }
}

// ---------------- fused silu + modulation GEMV ----------------
__global__ void mod_gemv2(const float* __restrict__ w0, const float* __restrict__ b0,
                          const float* __restrict__ t0,
                          const float* __restrict__ w1, const float* __restrict__ b1,
                          const float* __restrict__ t1){
  __shared__ float ssil[DIM];
  const int stream = blockIdx.y;
  const float* w = stream ? w1 : w0;
  const float* b = stream ? b1 : b0;
  const float* t = stream ? t1 : t0;
  for (int i=threadIdx.x; i<DIM; i+=256){
    float x = t[i]; ssil[i] = x/(1.f+expf(-x));
  }
  __syncthreads();
  int warp = (blockIdx.x*blockDim.x + threadIdx.x) >> 5;
  int lane = threadIdx.x & 31;
  if (warp >= 3*DIM) return;
  const float4* wv = (const float4*)(w + (size_t)warp*DIM);
  const float4* sv = (const float4*)ssil;
  float acc = 0.f;
  for (int i = lane; i < DIM/4; i += 32){
    float4 a = wv[i], c = sv[i];
    acc += a.x*c.x + a.y*c.y + a.z*c.z + a.w*c.w;
  }
#pragma unroll
  for (int o=16;o;o>>=1) acc += __shfl_xor_sync(0xffffffffu, acc, o);
  if (!lane) g_mod[stream][warp] = acc + b[warp];
}

// ---------------- LayerNorm + modulate (half out) ----------------
__global__ void ln_mod2(const float* __restrict__ x0, const float* __restrict__ x1){
  __shared__ float sh[66];
  const int stream = blockIdx.y;
  const float* x = stream ? x1 : x0;
  int s = blockIdx.x;
  const float* row = x + (size_t)s*DIM;
  float sum=0.f, sq=0.f;
  for (int i=threadIdx.x; i<DIM; i+=256){ float v=row[i]; sum+=v; sq+=v*v; }
#pragma unroll
  for (int o=16;o;o>>=1){
    sum += __shfl_xor_sync(0xffffffffu,sum,o);
    sq  += __shfl_xor_sync(0xffffffffu,sq,o);
  }
  int w=threadIdx.x>>5, l=threadIdx.x&31;
  if (!l){ sh[w]=sum; sh[32+w]=sq; }
  __syncthreads();
  if (threadIdx.x==0){
    float a=0.f,b=0.f;
#pragma unroll
    for (int i=0;i<8;i++){ a+=sh[i]; b+=sh[32+i]; }
    sh[64]=a; sh[65]=b;
  }
  __syncthreads();
  float mu = sh[64]*(1.f/DIM);
  float var = sh[65]*(1.f/DIM) - mu*mu;
  float rstd = rsqrtf(var + 1e-6f);
  const float* shift = g_mod[stream];
  const float* scale = g_mod[stream] + DIM;
  __half* out = g_nh[stream] + (size_t)s*DIM;
  for (int i=threadIdx.x; i<DIM; i+=256)
    out[i] = __float2half_rn((row[i]-mu)*rstd*(1.f+scale[i]) + shift[i]);
}

// ---------------- per-(s,head) RMS + RoPE on half buffers ----------------
__global__ void rmsrope_kernel(__half* __restrict__ qkvbase,
                               const float* __restrict__ w0, const float* __restrict__ w1,
                               const float* __restrict__ w2, const float* __restrict__ w3,
                               const float* __restrict__ cosb, const float* __restrict__ sinb){
  const int bufsel[4] = {0,1,3,4};
  int b = blockIdx.y;
  __half* buf = qkvbase + (size_t)bufsel[b]*SEQ*DIM;
  const float* w = (b==0)?w0:(b==1)?w1:(b==2)?w2:w3;
  int idx  = blockIdx.x*blockDim.x + threadIdx.x;
  int warp = idx >> 5, lane = idx & 31;
  int s = warp / NHDS, h = warp % NHDS;
  uint2* row = (uint2*)(buf + (size_t)s*DIM + h*HD);
  uint2 raw = row[lane];
  __half2 p01 = *reinterpret_cast<__half2*>(&raw.x);
  __half2 p23 = *reinterpret_cast<__half2*>(&raw.y);
  float v0=__low2float(p01), v1=__high2float(p01);
  float v2=__low2float(p23), v3=__high2float(p23);
  float sq = v0*v0+v1*v1+v2*v2+v3*v3;
#pragma unroll
  for (int o=16;o;o>>=1) sq += __shfl_xor_sync(0xffffffffu, sq, o);
  float rstd = rsqrtf(sq*(1.f/HD) + 1e-6f);
  int d = lane*4;
  float4 wv = *(const float4*)(w + d);
  float4 cv = *(const float4*)(cosb + s*HD + d);
  float4 sv = *(const float4*)(sinb + s*HD + d);
  float x0=v0*rstd*wv.x, x1=v1*rstd*wv.y, x2=v2*rstd*wv.z, x3=v3*rstd*wv.w;
  float o0 = x0*cv.x - x1*sv.x;
  float o1 = x1*cv.y + x0*sv.y;
  float o2 = x2*cv.z - x3*sv.z;
  float o3 = x3*cv.w + x2*sv.w;
  __half2 q01 = __floats2half2_rn(o0,o1);
  __half2 q23 = __floats2half2_rn(o2,o3);
  raw.x = *reinterpret_cast<uint32_t*>(&q01);
  raw.y = *reinterpret_cast<uint32_t*>(&q23);
  row[lane] = raw;
}

// ---------------- row softmax, smem-cached ----------------
__global__ void softmax_kernel(__half* __restrict__ p){
  __shared__ __half2 srow[SEQ/2];
  __shared__ float sh[36];
  __half2* row = (__half2*)(p + (size_t)blockIdx.x*SEQ);
  int tid=threadIdx.x, w=tid>>5, l=tid&31;
  float m = -1e30f;
#pragma unroll
  for (int i=tid;i<SEQ/2;i+=256){
    __half2 v = row[i];
    srow[i] = v;
    m = fmaxf(m, fmaxf(__low2float(v), __high2float(v)));
  }
#pragma unroll
  for (int o=16;o;o>>=1) m = fmaxf(m, __shfl_xor_sync(0xffffffffu,m,o));
  if (!l) sh[w]=m;
  __syncthreads();
  if (tid==0){ float mm=sh[0]; for(int i=1;i<8;i++) mm=fmaxf(mm,sh[i]); sh[32]=mm; }
  __syncthreads();
  m = sh[32];
  float sum=0.f;
#pragma unroll
  for (int i=tid;i<SEQ/2;i+=256){
    __half2 v = srow[i];
    float e0 = expf(__low2float(v)-m);
    float e1 = expf(__high2float(v)-m);
    srow[i] = __floats2half2_rn(e0,e1);
    sum += e0+e1;
  }
#pragma unroll
  for (int o=16;o;o>>=1) sum += __shfl_xor_sync(0xffffffffu,sum,o);
  if (!l) sh[8+w]=sum;
  __syncthreads();
  if (tid==0){ float ss=0.f; for(int i=0;i<8;i++) ss+=sh[8+i]; sh[33]=ss; }
  __syncthreads();
  float inv = 1.f/sh[33];
#pragma unroll
  for (int i=tid;i<SEQ/2;i+=256){
    __half2 v = srow[i];
    row[i] = __floats2half2_rn(__low2float(v)*inv, __high2float(v)*inv);
  }
}

// ---------------- add PV-cross scratch into hcat0 attn columns ----------------
__global__ void add_cross(const __half* __restrict__ cross, __half* __restrict__ hcat){
  int idx = blockIdx.x*blockDim.x + threadIdx.x;      // over SEQ*DIM/2 half2
  if (idx >= SEQ*DIM/2) return;
  int rw = idx / (DIM/2), cl = idx % (DIM/2);
  __half2 a = ((const __half2*)cross)[idx];
  __half2* dst = (__half2*)hcat + (size_t)rw*(CATD/2) + cl;
  __half2 b = *dst;
  *dst = __floats2half2_rn(__low2float(a)+__low2float(b), __high2float(a)+__high2float(b));
}

// ---------------- combine out-proj partials ----------------
__global__ void combine_out(const float* __restrict__ parts, const float* __restrict__ outb,
                            const float* __restrict__ gates, const float* __restrict__ hs,
                            const float* __restrict__ hsc, float* __restrict__ out){
  const long long SD = (long long)SEQ*DIM;
  long long i4 = (long long)blockIdx.x*blockDim.x + threadIdx.x;
  if (i4 >= (2*SD)/4) return;
  long long i = i4*4;
  int stream = (i >= SD);
  long long li = i - (long long)stream*SD;
  int col = (int)(li % DIM);
  const float4 p1 = *(const float4*)(parts + (2*stream+0)*SD + li);
  const float4 p2 = *(const float4*)(parts + (2*stream+1)*SD + li);
  const float4 bb = *(const float4*)(outb + col);
  const float4 gg = *(const float4*)(gates + (size_t)stream*3*DIM + col);
  const float4 rr = *(const float4*)((stream ? hsc : hs) + li);
  float4 o;
  o.x = rr.x + gg.x*(p1.x+p2.x+bb.x);
  o.y = rr.y + gg.y*(p1.y+p2.y+bb.y);
  o.z = rr.z + gg.z*(p1.z+p2.z+bb.z);
  o.w = rr.w + gg.w*(p1.w+p2.w+bb.w);
  *(float4*)(out + i) = o;
}

// ================ 3-stage pipelined FP16 GEMM (m16n8k16, fp32 acc) ================
#define AST   72
#define BST1  136
#define STG_H 18432
#define STG_B 36864
template<int BM>
__global__ __launch_bounds__(256,2) void gemm_h(
    const __half* __restrict__ A,  const __half* __restrict__ A2, const __half* __restrict__ A3,
    int lda, long long bsA,
    const __half* __restrict__ B,  const __half* __restrict__ B2, const __half* __restrict__ B3,
    int ldb, long long bsB,
    __half* __restrict__ C,  __half* __restrict__ C2, __half* __restrict__ C3,
    int ldc1, int ldc2, int ldc3, long long bsC,
    float* __restrict__ Cf, long long bsCf,
    int zs1, int zs2,
    int K,
    const float* __restrict__ bias, int bsBias, int epi, float alpha)
{
  extern __shared__ __half smh[];
  const int z = blockIdx.z;
  int ldc = ldc1;
  {
    long long zo;
    if (z < zs1){ zo = z; }
    else if (z < zs2){ A = A2; B = B2; C = C2; ldc = ldc2; zo = z - zs1; }
    else { A = A3; B = B3; C = C3; ldc = ldc3; zo = z - zs2; }
    A += zo*bsA;  B += zo*bsB;  C += zo*bsC;
  }
  if (Cf) Cf += (long long)z*bsCf;
  if (bias) bias += (long long)z*bsBias;
  const int bm0 = blockIdx.y*128, bn0 = blockIdx.x*128;
  const int tid = threadIdx.x;
  const int warp = tid>>5, lane = tid&31;
  const int wm = warp&1, wn = warp>>1;
  const int g = lane>>2, t = lane&3;
  const int j = lane>>3;

  const uint32_t smemBase = (uint32_t)__cvta_generic_to_shared(smh);
  const uint32_t aBase  = smemBase + (uint32_t)(((wm*64 + (j&1)*8 + (lane&7))*AST + (j>>1)*8)<<1);
  const uint32_t bBase0 = smemBase + (uint32_t)((9216 + (wn*32 + (j>>1)*8 + (lane&7))*AST + (j&1)*8)<<1);
  const uint32_t bBase1 = smemBase + (uint32_t)((9216 + ((j&1)*8 + (lane&7))*BST1 + wn*32 + (j>>1)*8)<<1);

  auto load_tile = [&](int kt, int buf){
    __half* As = smh + buf*STG_H;
    __half* Bs = As + 9216;
    const int k0 = kt<<6;
    {
      const int c8=(tid&7)*8, r=tid>>3;
#pragma unroll
      for (int it=0; it<4; it++){
        int row=r+it*32;
        cpa16(As + row*AST + c8, A + (long long)(bm0+row)*lda + (k0+c8));
      }
    }
    if (BM==0){
      const int c8=(tid&7)*8, r=tid>>3;
#pragma unroll
      for (int it=0; it<4; it++){
        int row=r+it*32;
        cpa16(Bs + row*AST + c8, B + (long long)(bn0+row)*ldb + (k0+c8));
      }
    } else {
      const int n8=(tid&15)*8, r=tid>>4;
#pragma unroll
      for (int it=0; it<4; it++){
        int kk=r+it*16;
        cpa16(Bs + kk*BST1 + n8, B + (long long)(k0+kk)*ldb + (bn0+n8));
      }
    }
  };

  float acc[4][4][4];
#pragma unroll
  for (int a=0;a<4;a++)
#pragma unroll
    for (int b=0;b<4;b++)
#pragma unroll
      for (int c=0;c<4;c++) acc[a][b][c]=0.f;

  const int KT = K >> 6;
  load_tile(0,0); cpcommit();
  if (KT > 1){ load_tile(1,1); cpcommit(); }
  int cur = 0, nxt = 2;

  for (int kt=0; kt<KT; kt++){
    if (kt+1 < KT) cpwait<1>(); else cpwait<0>();
    __syncthreads();
    if (kt+2 < KT){
      load_tile(kt+2, nxt); cpcommit();
      nxt = (nxt==2)?0:nxt+1;
    }
    const uint32_t stByte = cur*STG_B;

#pragma unroll
    for (int kk=0; kk<4; kk++){
      const uint32_t kByte = stByte + kk*32;
      uint32_t a[4][4];
#pragma unroll
      for (int mt=0; mt<4; mt++)
        ldsm4(a[mt][0],a[mt][1],a[mt][2],a[mt][3], aBase + mt*2304u + kByte);

      uint32_t b0[4], b1[4];
      if (BM==0){
#pragma unroll
        for (int p=0; p<2; p++){
          uint32_t r0,r1,r2,r3;
          ldsm4(r0,r1,r2,r3, bBase0 + p*2304u + kByte);
          b0[2*p]=r0; b1[2*p]=r1; b0[2*p+1]=r2; b1[2*p+1]=r3;
        }
      } else {
#pragma unroll
        for (int p=0; p<2; p++){
          uint32_t r0,r1,r2,r3;
          ldsm4t(r0,r1,r2,r3, bBase1 + p*32u + (stByte + kk*4352u));
          b0[2*p]=r0; b1[2*p]=r1; b0[2*p+1]=r2; b1[2*p+1]=r3;
        }
      }
#pragma unroll
      for (int mt=0; mt<4; mt++)
#pragma unroll
        for (int nt=0; nt<4; nt++)
          mma_h(acc[mt][nt], a[mt][0],a[mt][1],a[mt][2],a[mt][3], b0[nt],b1[nt]);
    }
    cur = (cur==2)?0:cur+1;
  }

#pragma unroll
  for (int mt=0; mt<4; mt++){
#pragma unroll
    for (int nt=0; nt<4; nt++){
#pragma unroll
      for (int i=0; i<4; i++){
        int row = bm0 + wm*64 + mt*16 + g + ((i&2)?8:0);
        int col = bn0 + wn*32 + nt*8 + t*2 + (i&1);
        long long idx = (long long)row*ldc + col;
        float v = acc[mt][nt][i];
        if (bias) v += bias[col];
        if (epi==0)      C[idx] = __float2half_rn(v);
        else if (epi==1) C[idx] = __float2half_rn(gelu_t(v));
        else if (epi==2) C[idx] = __float2half_rn(v*alpha);
        else if (epi==3) C[idx] = __float2half_rn(v + __half2float(C[idx]));
        else             Cf[idx] = v;
      }
    }
  }
}

// ---------------- host orchestration ----------------
struct GArgs {
  const __half *A,*A2,*A3; int lda; long long bsA;
  const __half *B,*B2,*B3; int ldb; long long bsB; int bmode;
  __half *C,*C2,*C3; int ldc, ldc2, ldc3; long long bsC;
  float* Cf; long long bsCf;
  int zs1, zs2, M, N, K, batch;
  const float* bias; int bsBias; int epi; float alpha;
  cudaStream_t st;
};
static void launch_g(const GArgs& a){
  dim3 grid(a.N/128, a.M/128, a.batch);
  size_t shm = STG_B*3;
#define GCALL(BM) gemm_h<BM><<<grid,256,shm,a.st>>>( \
      a.A,a.A2,a.A3,a.lda,a.bsA, a.B,a.B2,a.B3,a.ldb,a.bsB, \
      a.C,a.C2,a.C3,a.ldc,a.ldc2,a.ldc3,a.bsC, a.Cf,a.bsCf, a.zs1,a.zs2, a.K, \
      a.bias,a.bsBias,a.epi,a.alpha)
  if (a.bmode==0) GCALL(0); else GCALL(1);
#undef GCALL
}

extern "C" void kernel_launch(void* const* d_in, const int* in_sizes, int n_in,
                              void* d_out, int out_size){
  const float* hs     = (const float*)d_in[0];
  const float* temb   = (const float*)d_in[1];
  const float* hsc    = (const float*)d_in[2];
  const float* tembc  = (const float*)d_in[3];
  const float* ropec  = (const float*)d_in[4];
  const float* ropes  = (const float*)d_in[5];
  const float* norm_w = (const float*)d_in[6];
  const float* norm_b = (const float*)d_in[7];
  const float* normc_w= (const float*)d_in[8];
  const float* normc_b= (const float*)d_in[9];
  const float* mlp_w  = (const float*)d_in[10];
  const float* mlp_b  = (const float*)d_in[11];
  const float* out_w  = (const float*)d_in[12];
  const float* out_b  = (const float*)d_in[13];
  const float* q_w    = (const float*)d_in[14];
  const float* q_b    = (const float*)d_in[15];
  const float* k_w    = (const float*)d_in[16];
  const float* k_b    = (const float*)d_in[17];
  const float* v_w    = (const float*)d_in[18];
  const float* v_b    = (const float*)d_in[19];
  const float* rms_q  = (const float*)d_in[20];
  const float* rms_k  = (const float*)d_in[21];
  const float* qc_w   = (const float*)d_in[22];
  const float* qc_b   = (const float*)d_in[23];
  const float* kc_w   = (const float*)d_in[24];
  const float* kc_b   = (const float*)d_in[25];
  const float* vc_w   = (const float*)d_in[26];
  const float* vc_b   = (const float*)d_in[27];
  const float* rms_qc = (const float*)d_in[28];
  const float* rms_kc = (const float*)d_in[29];
  float* out = (float*)d_out;

  static __half *p_nh=nullptr, *p_qkv=nullptr, *p_sc=nullptr, *p_hc=nullptr, *p_wh=nullptr, *p_pvx=nullptr;
  static float *p_mod=nullptr, *p_bias=nullptr;
  static cudaStream_t s2;
  static cudaEvent_t evF, evQKV, evLN, evMLP;
  if (!p_nh){
    cudaGetSymbolAddress((void**)&p_nh,  g_nh);
    cudaGetSymbolAddress((void**)&p_qkv, g_qkv);
    cudaGetSymbolAddress((void**)&p_sc,  g_sc);
    cudaGetSymbolAddress((void**)&p_hc,  g_hcat);
    cudaGetSymbolAddress((void**)&p_wh,  g_wh);
    cudaGetSymbolAddress((void**)&p_pvx, g_pvx);
    cudaGetSymbolAddress((void**)&p_mod, g_mod);
    cudaGetSymbolAddress((void**)&p_bias,g_bias);
    cudaFuncSetAttribute(gemm_h<0>, cudaFuncAttributeMaxDynamicSharedMemorySize, STG_B*3);
    cudaFuncSetAttribute(gemm_h<1>, cudaFuncAttributeMaxDynamicSharedMemorySize, STG_B*3);
    cudaStreamCreateWithFlags(&s2, cudaStreamNonBlocking);
    cudaEventCreateWithFlags(&evF,   cudaEventDisableTiming);
    cudaEventCreateWithFlags(&evQKV, cudaEventDisableTiming);
    cudaEventCreateWithFlags(&evLN,  cudaEventDisableTiming);
    cudaEventCreateWithFlags(&evMLP, cudaEventDisableTiming);
  }
  const size_t SD = (size_t)SEQ*DIM;
  __half* nh0 = p_nh;          __half* nh1 = p_nh + SD;
  __half* q   = p_qkv + 0*SD;  __half* kb_ = p_qkv + 1*SD;  __half* v   = p_qkv + 2*SD;
  __half* qc  = p_qkv + 3*SD;  __half* kc  = p_qkv + 4*SD;  __half* vc  = p_qkv + 5*SD;
  __half* hcat0 = p_hc;        __half* hcat1 = p_hc + (size_t)SEQ*CATD;
  float* gate0 = p_mod + 2*DIM;
  const long long SS = (long long)SEQ*SEQ;
  __half* sc_ctrl  = p_sc + 24*SS;
  __half* sc_cross = p_sc + 48*SS;
  float* parts = (float*)p_sc;

  __half* wh_q  = p_wh + 0*WC_QKV;
  __half* wh_qc = p_wh + 3*WC_QKV;
  __half* wh_ml = p_wh + 6*WC_QKV;
  __half* wh_ou = p_wh + 6*WC_QKV + WC_MLP;

  // ---- fork ----
  cudaEventRecord(evF, 0);
  cudaStreamWaitEvent(s2, evF, 0);
  // s2: qkv cvt + bias pack (needed by QKV on main), then out cvt, then MLP
  { int n4 = (int)(WC_QKV/4); dim3 grid((n4+255)/256, 6);
    cvt6_h<<<grid,256,0,s2>>>(q_w,k_w,v_w,qc_w,kc_w,vc_w, p_wh, n4); }
  pack_bias_kernel<<<(DIM+255)/256,256,0,s2>>>(q_b,k_b,v_b,qc_b,kc_b,vc_b);
  cudaEventRecord(evQKV, s2);
  { int n4 = (int)(WC_OUT/4); cvt_h<<<(n4+255)/256,256,0,s2>>>(out_w, wh_ou, n4); }

  // main: mlp cvt + modulation + ln
  { int n4 = (int)(WC_MLP/4); cvt_h<<<(n4+255)/256,256>>>(mlp_w, wh_ml, n4); }
  { dim3 grid((3*DIM)/8, 2); mod_gemv2<<<grid,256>>>(norm_w,norm_b,temb, normc_w,normc_b,tembc); }
  { dim3 grid(SEQ,2); ln_mod2<<<grid,256>>>(hs, hsc); }
  cudaEventRecord(evLN, 0);

  // s2: MLP both streams, z=2 (concurrent with attention chain on main)
  cudaStreamWaitEvent(s2, evLN, 0);
  { GArgs a{};
    a.A=nh0; a.A2=a.A3=nh0; a.lda=DIM; a.bsA=(long long)SD;
    a.B=wh_ml; a.B2=a.B3=wh_ml; a.ldb=DIM; a.bsB=0; a.bmode=0;
    a.C=hcat0+DIM; a.C2=a.C3=a.C; a.ldc=a.ldc2=a.ldc3=CATD; a.bsC=(long long)SEQ*CATD;
    a.Cf=nullptr; a.bsCf=0;
    a.zs1=2; a.zs2=2; a.M=SEQ; a.N=MLPD; a.K=DIM; a.batch=2;
    a.bias=mlp_b; a.bsBias=0; a.epi=1; a.alpha=0.f; a.st=s2;
    launch_g(a); }
  cudaEventRecord(evMLP, s2);

  // main: attention chain
  cudaStreamWaitEvent(0, evQKV, 0);
  { GArgs a{};
    a.A=nh0; a.A2=nh1; a.A3=nh1; a.lda=DIM; a.bsA=0;
    a.B=wh_q; a.B2=wh_qc; a.B3=wh_qc; a.ldb=DIM; a.bsB=(long long)WC_QKV; a.bmode=0;
    a.C=q; a.C2=qc; a.C3=qc; a.ldc=a.ldc2=a.ldc3=DIM; a.bsC=(long long)SD;
    a.Cf=nullptr; a.bsCf=0;
    a.zs1=3; a.zs2=6; a.M=SEQ; a.N=DIM; a.K=DIM; a.batch=6;
    a.bias=p_bias; a.bsBias=DIM; a.epi=0; a.alpha=0.f; a.st=0;
    launch_g(a); }
  { dim3 grid(3072,4); rmsrope_kernel<<<grid,256>>>(p_qkv, rms_q, rms_k, rms_qc, rms_kc, ropec, ropes); }
  { GArgs a{};
    a.A=q;  a.A2=qc; a.A3=q;  a.lda=DIM; a.bsA=HD;
    a.B=kb_; a.B2=kc; a.B3=kc; a.ldb=DIM; a.bsB=HD; a.bmode=0;
    a.C=p_sc; a.C2=sc_ctrl; a.C3=sc_cross; a.ldc=a.ldc2=a.ldc3=SEQ; a.bsC=SS;
    a.Cf=nullptr; a.bsCf=0;
    a.zs1=24; a.zs2=48; a.M=SEQ; a.N=SEQ; a.K=HD; a.batch=72;
    a.bias=nullptr; a.bsBias=0; a.epi=2; a.alpha=INV_SQRT_HD; a.st=0;
    launch_g(a); }
  softmax_kernel<<<72*SEQ,256>>>(p_sc);
  { GArgs a{};
    a.A=p_sc; a.A2=sc_ctrl; a.A3=sc_cross; a.lda=SEQ; a.bsA=SS;
    a.B=v; a.B2=vc; a.B3=vc; a.ldb=DIM; a.bsB=HD; a.bmode=1;
    a.C=hcat0; a.C2=hcat1; a.C3=p_pvx; a.ldc=CATD; a.ldc2=CATD; a.ldc3=DIM; a.bsC=HD;
    a.Cf=nullptr; a.bsCf=0;
    a.zs1=24; a.zs2=48; a.M=SEQ; a.N=HD; a.K=SEQ; a.batch=72;
    a.bias=nullptr; a.bsBias=0; a.epi=0; a.alpha=0.f; a.st=0;
    launch_g(a); }
  add_cross<<<(SEQ*DIM/2+255)/256,256>>>(p_pvx, hcat0);

  // join MLP, then out-projection split-K + combine
  cudaStreamWaitEvent(0, evMLP, 0);
  { GArgs a{};
    a.A=hcat0; a.A2=hcat0+KHALF; a.A3=hcat1; a.lda=CATD; a.bsA=KHALF;
    a.B=wh_ou; a.B2=wh_ou+KHALF; a.B3=wh_ou; a.ldb=CATD; a.bsB=KHALF; a.bmode=0;
    a.C=nullptr; a.C2=a.C3=nullptr; a.ldc=a.ldc2=a.ldc3=DIM; a.bsC=0;
    a.Cf=parts; a.bsCf=(long long)SD;
    a.zs1=1; a.zs2=2; a.M=SEQ; a.N=DIM; a.K=KHALF; a.batch=4;
    a.bias=nullptr; a.bsBias=0; a.epi=5; a.alpha=0.f; a.st=0;
    launch_g(a); }
  { long long n4 = (2*(long long)SD)/4;
    combine_out<<<(unsigned)((n4+255)/256),256>>>(parts, out_b, gate0, hs, hsc, out); }
}